// round 15
// baseline (speedup 1.0000x reference)
#include <cuda_runtime.h>
#include <cuda_bf16.h>

#define BB 16
#define NN 4096
#define DD 512
#define KK 128
#define REGC 1e-6f

typedef unsigned long long ull;

__device__ __forceinline__ ull pack2(float x, float y) {
    ull r; asm("mov.b64 %0, {%1, %2};" : "=l"(r) : "f"(x), "f"(y)); return r;
}
__device__ __forceinline__ void unpack2(ull v, float& lo, float& hi) {
    asm("mov.b64 {%0, %1}, %2;" : "=f"(lo), "=f"(hi) : "l"(v));
}
__device__ __forceinline__ void ffma2(ull& d, ull a, ull b) {
    asm("fma.rn.f32x2 %0, %1, %2, %0;" : "+l"(d) : "l"(a), "l"(b));
}
__device__ __forceinline__ unsigned smem_u32(const void* p) {
    unsigned a;
    asm("{ .reg .u64 t; cvta.to.shared.u64 t, %1; cvt.u32.u64 %0, t; }" : "=r"(a) : "l"(p));
    return a;
}
__device__ __forceinline__ void ldm4(unsigned* r, unsigned addr) {
    asm volatile("ldmatrix.sync.aligned.m8n8.x4.shared.b16 {%0,%1,%2,%3}, [%4];"
                 : "=r"(r[0]), "=r"(r[1]), "=r"(r[2]), "=r"(r[3]) : "r"(addr));
}
__device__ __forceinline__ void mma_bf16(float* d, const unsigned* a, const unsigned* b) {
    asm volatile(
        "mma.sync.aligned.m16n8k16.row.col.f32.bf16.bf16.f32 "
        "{%0,%1,%2,%3}, {%4,%5,%6,%7}, {%8,%9}, {%0,%1,%2,%3};"
        : "+f"(d[0]), "+f"(d[1]), "+f"(d[2]), "+f"(d[3])
        : "r"(a[0]), "r"(a[1]), "r"(a[2]), "r"(a[3]), "r"(b[0]), "r"(b[1]));
}
__device__ __forceinline__ float lds_f32(unsigned a) {
    float v; asm volatile("ld.shared.f32 %0, [%1];" : "=f"(v) : "r"(a)); return v;
}
__device__ __forceinline__ float4 lds_f128(unsigned a) {
    float4 v;
    asm volatile("ld.shared.v4.f32 {%0,%1,%2,%3}, [%4];"
                 : "=f"(v.x), "=f"(v.y), "=f"(v.z), "=f"(v.w) : "r"(a));
    return v;
}
__device__ __forceinline__ uint4 lds_u128(unsigned a) {
    uint4 v;
    asm volatile("ld.shared.v4.b32 {%0,%1,%2,%3}, [%4];"
                 : "=r"(v.x), "=r"(v.y), "=r"(v.z), "=r"(v.w) : "r"(a));
    return v;
}
__device__ __forceinline__ void sts128(unsigned a, unsigned r0, unsigned r1,
                                       unsigned r2, unsigned r3) {
    asm volatile("st.shared.v4.b32 [%0], {%1,%2,%3,%4};"
                 :: "r"(a), "r"(r0), "r"(r1), "r"(r2), "r"(r3) : "memory");
}
__device__ __forceinline__ void sts_v2f(unsigned a, float x, float y) {
    asm volatile("st.shared.v2.f32 [%0], {%1,%2};" :: "r"(a), "f"(x), "f"(y) : "memory");
}
#define SWZ(o) ((o) ^ (((o) >> 3) & 0x70))

// Scratch
__device__ float g_S[2 * BB * KK * KK];
__device__ float g_Sinv[2 * BB * KK * KK];
__device__ float g_R[BB * KK * KK];
__device__ float g_RT[BB * KK * KK];
__device__ __nv_bfloat16 g_Ehi[2 * BB * KK * NN];
__device__ __nv_bfloat16 g_Elo[2 * BB * KK * NN];
__device__ __nv_bfloat16 g_ABhi[2 * BB * KK * DD];
__device__ __nv_bfloat16 g_ABlo[2 * BB * KK * DD];

__device__ __forceinline__ void split1(float x, unsigned short& h, unsigned short& l) {
    __nv_bfloat16 hb = __float2bfloat16_rn(x);
    float r = x - __bfloat162float(hb);
    __nv_bfloat16 lb = __float2bfloat16_rn(r);
    h = __bfloat16_as_ushort(hb);
    l = __bfloat16_as_ushort(lb);
}
__device__ __forceinline__ float bf2f(unsigned short u) {
    return __bfloat162float(__ushort_as_bfloat16(u));
}

// ---------------------------------------------------------------------------
// split_E (unchanged)
// ---------------------------------------------------------------------------
__global__ void split_E(const float* __restrict__ ex, const float* __restrict__ ey) {
    int w = blockIdx.y;
    const float* E = w ? ey : ex;
    size_t i4 = (size_t)blockIdx.x * 256 + threadIdx.x;
    float4 t = *((const float4*)E + i4);
    unsigned short h0, h1, h2, h3, l0, l1, l2, l3;
    split1(t.x, h0, l0); split1(t.y, h1, l1); split1(t.z, h2, l2); split1(t.w, h3, l3);
    ull hp = (ull)h0 | ((ull)h1 << 16) | ((ull)h2 << 32) | ((ull)h3 << 48);
    ull lp = (ull)l0 | ((ull)l1 << 16) | ((ull)l2 << 32) | ((ull)l3 << 48);
    size_t o = (size_t)w * (BB * KK * NN) + i4 * 4;
    *(ull*)(g_Ehi + o) = hp;
    *(ull*)(g_Elo + o) = lp;
}

// ---------------------------------------------------------------------------
// mma_proj (unchanged)
// ---------------------------------------------------------------------------
#define CONV_BH 0
#define CONV_BL 16384
#define STAGE0 32768
#define STAGE_SZ 65536
#define MMA_SMEM (1024 + STAGE0 + 3 * STAGE_SZ)

__global__ void __launch_bounds__(256, 1) mma_proj(const float* __restrict__ fx,
                                                   const float* __restrict__ fy) {
    extern __shared__ char smraw[];
    unsigned base = (smem_u32(smraw) + 1023) & ~1023u;
    int tid = threadIdx.x, wid = tid >> 5, lane = tid & 31;

    int p = blockIdx.y; int w = p >> 4, b = p & 15;
    int n0 = blockIdx.x * 128;
    const __nv_bfloat16* Eh = g_Ehi + (size_t)p * KK * NN;
    const __nv_bfloat16* El = g_Elo + (size_t)p * KK * NN;
    const float* Ff = (w ? fy : fx) + (size_t)b * NN * DD + n0;
    size_t cbase = (size_t)p * KK * DD + n0;

    int wm = (wid & 1) * 64, wn = (wid >> 1) * 32;

    float acc[4][4][4];
#pragma unroll
    for (int mt = 0; mt < 4; mt++)
#pragma unroll
        for (int nt = 0; nt < 4; nt++)
#pragma unroll
            for (int i = 0; i < 4; i++) acc[mt][nt][i] = 0.0f;

    unsigned msk = (unsigned)((lane & 7) << 4);
    unsigned a_c0 = (unsigned)((lane >> 4) * 16);
    unsigned b_c0 = (unsigned)(((lane >> 3) & 1) * 16);
    unsigned a_row[4], b_row[2];
#pragma unroll
    for (int mt = 0; mt < 4; mt++)
        a_row[mt] = (unsigned)((wm + mt * 16 + (lane & 15)) * 128);
#pragma unroll
    for (int np = 0; np < 2; np++)
        b_row[np] = (unsigned)((wn + np * 16 + ((lane >> 4) << 3) + (lane & 7)) * 128);

    int cd = tid & 127, ckg = tid >> 7;

    auto issue = [&](int c) {
        unsigned stage = base + STAGE0 + (unsigned)(c % 3) * STAGE_SZ;
        int k0 = c * 64;
#pragma unroll
        for (int u = 0; u < 8; u++) {
            int tile = u >> 2;
            int v = tid + (u & 3) * 256;
            int r = v >> 3, s = v & 7;
            unsigned sa = stage + tile * 16384 + SWZ((unsigned)(r * 128 + s * 16));
            const __nv_bfloat16* g = (tile ? El : Eh) + (size_t)r * NN + k0 + s * 8;
            asm volatile("cp.async.cg.shared.global [%0], [%1], 16;"
                         :: "r"(sa), "l"(g) : "memory");
        }
#pragma unroll
        for (int u = 0; u < 8; u++) {
            int v = tid + u * 256;
            int r = v >> 5, s = v & 31;
            unsigned sa = stage + 32768 + (unsigned)(r * 512 + s * 16);
            const float* g = Ff + (size_t)(k0 + r) * DD + s * 4;
            asm volatile("cp.async.cg.shared.global [%0], [%1], 16;"
                         :: "r"(sa), "l"(g) : "memory");
        }
        asm volatile("cp.async.commit_group;" ::: "memory");
    };

    issue(0);
    issue(1);
    for (int c = 0; c < 64; c++) {
        if (c < 63)
            asm volatile("cp.async.wait_group 1;" ::: "memory");
        else
            asm volatile("cp.async.wait_group 0;" ::: "memory");
        __syncthreads();

        unsigned stage = base + STAGE0 + (unsigned)(c % 3) * STAGE_SZ;
        {
            unsigned fpb = stage + 32768;
#pragma unroll
            for (int kq = 0; kq < 4; kq++) {
                int kstart = ckg * 8 + kq * 16;
                unsigned hw[4], lw[4];
#pragma unroll
                for (int w2 = 0; w2 < 4; w2++) {
                    float x0 = lds_f32(fpb + (unsigned)(((kstart + 2 * w2) * 128 + cd) * 4));
                    float x1 = lds_f32(fpb + (unsigned)(((kstart + 2 * w2 + 1) * 128 + cd) * 4));
                    unsigned short h0, l0, h1, l1;
                    split1(x0, h0, l0); split1(x1, h1, l1);
                    hw[w2] = (unsigned)h0 | ((unsigned)h1 << 16);
                    lw[w2] = (unsigned)l0 | ((unsigned)l1 << 16);
                }
                unsigned off = SWZ((unsigned)(cd * 128 + kstart * 2));
                sts128(base + CONV_BH + off, hw[0], hw[1], hw[2], hw[3]);
                sts128(base + CONV_BL + off, lw[0], lw[1], lw[2], lw[3]);
            }
        }
        __syncthreads();
        if (c + 2 < 64) issue(c + 2);

        unsigned sAh = stage, sAl = stage + 16384;
        unsigned sBh = base + CONV_BH, sBl = base + CONV_BL;
#pragma unroll
        for (int kk = 0; kk < 4; kk++) {
            unsigned ca = (a_c0 + (unsigned)(kk * 32)) ^ msk;
            unsigned cb = (b_c0 + (unsigned)(kk * 32)) ^ msk;
            unsigned ah[4][4], al[4][4], bh[2][4], bl[2][4];
#pragma unroll
            for (int mt = 0; mt < 4; mt++) {
                ldm4(ah[mt], sAh + a_row[mt] + ca);
                ldm4(al[mt], sAl + a_row[mt] + ca);
            }
#pragma unroll
            for (int np = 0; np < 2; np++) {
                ldm4(bh[np], sBh + b_row[np] + cb);
                ldm4(bl[np], sBl + b_row[np] + cb);
            }
#pragma unroll
            for (int mt = 0; mt < 4; mt++)
#pragma unroll
                for (int nt = 0; nt < 4; nt++)
                    mma_bf16(acc[mt][nt], ah[mt], &bh[nt >> 1][(nt & 1) * 2]);
#pragma unroll
            for (int mt = 0; mt < 4; mt++)
#pragma unroll
                for (int nt = 0; nt < 4; nt++)
                    mma_bf16(acc[mt][nt], ah[mt], &bl[nt >> 1][(nt & 1) * 2]);
#pragma unroll
            for (int mt = 0; mt < 4; mt++)
#pragma unroll
                for (int nt = 0; nt < 4; nt++)
                    mma_bf16(acc[mt][nt], al[mt], &bh[nt >> 1][(nt & 1) * 2]);
        }
    }

#pragma unroll
    for (int mt = 0; mt < 4; mt++) {
#pragma unroll
        for (int nt = 0; nt < 4; nt++) {
            int r0 = wm + mt * 16 + (lane >> 2);
            int c0 = wn + nt * 8 + (lane & 3) * 2;
            unsigned short h0, l0, h1, l1, h2, l2, h3, l3;
            split1(acc[mt][nt][0], h0, l0);
            split1(acc[mt][nt][1], h1, l1);
            split1(acc[mt][nt][2], h2, l2);
            split1(acc[mt][nt][3], h3, l3);
            size_t o01 = cbase + (size_t)r0 * DD + c0;
            size_t o23 = cbase + (size_t)(r0 + 8) * DD + c0;
            *(unsigned*)(g_ABhi + o01) = (unsigned)h0 | ((unsigned)h1 << 16);
            *(unsigned*)(g_ABlo + o01) = (unsigned)l0 | ((unsigned)l1 << 16);
            *(unsigned*)(g_ABhi + o23) = (unsigned)h2 | ((unsigned)h3 << 16);
            *(unsigned*)(g_ABlo + o23) = (unsigned)l2 | ((unsigned)l3 << 16);
        }
    }
}

// ---------------------------------------------------------------------------
// gemm_nt_hmma: S-only now. 32 CTAs (id = b*2 + mode, mode in {0,1}).
// ---------------------------------------------------------------------------
#define NTSTAGE_BYTES 65536
#define NT_SMEM (1024 + 3 * NTSTAGE_BYTES)
__global__ void __launch_bounds__(256, 1) gemm_nt_hmma() {
    extern __shared__ char smraw[];
    unsigned base = (smem_u32(smraw) + 1023) & ~1023u;
    int tid = threadIdx.x, wid = tid >> 5, lane = tid & 31;

    int id = blockIdx.x;
    int b = id >> 1, mode = id & 1;
    size_t offA = (size_t)b * KK * DD;
    size_t offB = (size_t)(BB + b) * KK * DD;
    size_t offP = (mode == 0) ? offA : offB;
    const __nv_bfloat16* Ph = g_ABhi + offP;
    const __nv_bfloat16* Pl = g_ABlo + offP;
    float* C = g_S + (size_t)id * KK * KK;

    int wm = (wid & 1) * 64, wn = (wid >> 1) * 32;

    float acc[4][4][4];
#pragma unroll
    for (int mt = 0; mt < 4; mt++)
#pragma unroll
        for (int nt = 0; nt < 4; nt++)
#pragma unroll
            for (int i = 0; i < 4; i++) acc[mt][nt][i] = 0.0f;

    unsigned msk = (unsigned)((lane & 7) << 4);
    unsigned a_c0 = (unsigned)((lane >> 4) * 16);
    unsigned b_c0 = (unsigned)(((lane >> 3) & 1) * 16);
    unsigned a_row[4], b_row[2];
#pragma unroll
    for (int mt = 0; mt < 4; mt++)
        a_row[mt] = (unsigned)((wm + mt * 16 + (lane & 15)) * 128);
#pragma unroll
    for (int np = 0; np < 2; np++)
        b_row[np] = (unsigned)((wn + np * 16 + ((lane >> 4) << 3) + (lane & 7)) * 128);

    auto issue = [&](int c) {
        unsigned stage = base + 1024 + (unsigned)(c % 3) * NTSTAGE_BYTES;
        int k0 = c * 64;
#pragma unroll
        for (int u = 0; u < 16; u++) {
            int tile = u >> 2;
            int v = tid + (u & 3) * 256;
            int r = v >> 3, s = v & 7;
            unsigned sa = stage + tile * 16384 + SWZ((unsigned)(r * 128 + s * 16));
            const __nv_bfloat16* g = ((tile & 1) ? Pl : Ph);
            g += (size_t)r * DD + k0 + s * 8;
            asm volatile("cp.async.cg.shared.global [%0], [%1], 16;"
                         :: "r"(sa), "l"(g) : "memory");
        }
        asm volatile("cp.async.commit_group;" ::: "memory");
    };

    issue(0);
    issue(1);
    for (int c = 0; c < 8; c++) {
        if (c < 7)
            asm volatile("cp.async.wait_group 1;" ::: "memory");
        else
            asm volatile("cp.async.wait_group 0;" ::: "memory");
        __syncthreads();
        if (c + 2 < 8) issue(c + 2);
        unsigned stage = base + 1024 + (unsigned)(c % 3) * NTSTAGE_BYTES;
        unsigned sAh = stage, sAl = stage + 16384, sBh = stage + 32768, sBl = stage + 49152;
#pragma unroll
        for (int kk = 0; kk < 4; kk++) {
            unsigned ca = (a_c0 + (unsigned)(kk * 32)) ^ msk;
            unsigned cb = (b_c0 + (unsigned)(kk * 32)) ^ msk;
            unsigned ah[4][4], al[4][4], bh[2][4], bl[2][4];
#pragma unroll
            for (int mt = 0; mt < 4; mt++) {
                ldm4(ah[mt], sAh + a_row[mt] + ca);
                ldm4(al[mt], sAl + a_row[mt] + ca);
            }
#pragma unroll
            for (int np = 0; np < 2; np++) {
                ldm4(bh[np], sBh + b_row[np] + cb);
                ldm4(bl[np], sBl + b_row[np] + cb);
            }
#pragma unroll
            for (int mt = 0; mt < 4; mt++)
#pragma unroll
                for (int nt = 0; nt < 4; nt++)
                    mma_bf16(acc[mt][nt], ah[mt], &bh[nt >> 1][(nt & 1) * 2]);
#pragma unroll
            for (int mt = 0; mt < 4; mt++)
#pragma unroll
                for (int nt = 0; nt < 4; nt++)
                    mma_bf16(acc[mt][nt], ah[mt], &bl[nt >> 1][(nt & 1) * 2]);
#pragma unroll
            for (int mt = 0; mt < 4; mt++)
#pragma unroll
                for (int nt = 0; nt < 4; nt++)
                    mma_bf16(acc[mt][nt], al[mt], &bh[nt >> 1][(nt & 1) * 2]);
        }
    }

    // S tiles live in the same smem after sBh/sBl of stage 1? (P == Q here: B-tiles
    // are loaded from the same Ph/Pl source; sBh used tiles 2,3 of issue)
#pragma unroll
    for (int mt = 0; mt < 4; mt++) {
#pragma unroll
        for (int nt = 0; nt < 4; nt++) {
            int r0 = wm + mt * 16 + (lane >> 2);
            int c0 = wn + nt * 8 + (lane & 3) * 2;
            float v0 = acc[mt][nt][0], v1 = acc[mt][nt][1];
            float v2 = acc[mt][nt][2], v3 = acc[mt][nt][3];
            if (r0 == c0) v0 += REGC;
            if (r0 == c0 + 1) v1 += REGC;
            if (r0 + 8 == c0) v2 += REGC;
            if (r0 + 8 == c0 + 1) v3 += REGC;
            C[r0 * KK + c0] = v0;
            C[r0 * KK + c0 + 1] = v1;
            C[(r0 + 8) * KK + c0] = v2;
            C[(r0 + 8) * KK + c0 + 1] = v3;
        }
    }
}

// ---------------------------------------------------------------------------
// invert_r: grid 48 x 512 threads.
//   id 0..31 : blocked GJ inversion of g_S[id] -> g_Sinv[id] (no mask).
//   id 32..47: R = B A^T (b = id-32), 16-warp HMMA -> g_R, g_RT (overlapped).
// ---------------------------------------------------------------------------
#define MST 132
#define CST 36
#define TST 36
#define IR_SMEM (1024 + 3 * STAGE_SZ)

__global__ void __launch_bounds__(512, 1) invert_r() {
    extern __shared__ float sm[];
    int tid = threadIdx.x, wid = tid >> 5, lane = tid & 31;
    int id = blockIdx.x;

    if (id >= 32) {
        // ----- R GEMM, 16 warps, warp tile 32x32 -----
        unsigned base = (smem_u32(sm) + 1023) & ~1023u;
        int b = id - 32;
        size_t offA = (size_t)b * KK * DD;
        size_t offB = (size_t)(BB + b) * KK * DD;
        const __nv_bfloat16* Ph = g_ABhi + offB;
        const __nv_bfloat16* Pl = g_ABlo + offB;
        const __nv_bfloat16* Qh = g_ABhi + offA;
        const __nv_bfloat16* Ql = g_ABlo + offA;
        float* C  = g_R  + (size_t)b * KK * KK;
        float* CT = g_RT + (size_t)b * KK * KK;

        int wm = (wid & 3) * 32, wn = (wid >> 2) * 32;
        float acc[2][4][4];
#pragma unroll
        for (int mt = 0; mt < 2; mt++)
#pragma unroll
            for (int nt = 0; nt < 4; nt++)
#pragma unroll
                for (int i = 0; i < 4; i++) acc[mt][nt][i] = 0.0f;

        unsigned msk = (unsigned)((lane & 7) << 4);
        unsigned a_c0 = (unsigned)((lane >> 4) * 16);
        unsigned b_c0 = (unsigned)(((lane >> 3) & 1) * 16);
        unsigned a_row[2], b_row[2];
#pragma unroll
        for (int mt = 0; mt < 2; mt++)
            a_row[mt] = (unsigned)((wm + mt * 16 + (lane & 15)) * 128);
#pragma unroll
        for (int np = 0; np < 2; np++)
            b_row[np] = (unsigned)((wn + np * 16 + ((lane >> 4) << 3) + (lane & 7)) * 128);

        auto issue = [&](int c) {
            unsigned stage = base + 1024 + (unsigned)(c % 3) * STAGE_SZ;
            int k0 = c * 64;
#pragma unroll
            for (int u = 0; u < 8; u++) {
                int tile = u >> 1;
                int v = tid + (u & 1) * 512;
                int r = v >> 3, s = v & 7;
                unsigned sa = stage + tile * 16384 + SWZ((unsigned)(r * 128 + s * 16));
                const __nv_bfloat16* g;
                if (tile == 0)      g = Ph;
                else if (tile == 1) g = Pl;
                else if (tile == 2) g = Qh;
                else                g = Ql;
                g += (size_t)r * DD + k0 + s * 8;
                asm volatile("cp.async.cg.shared.global [%0], [%1], 16;"
                             :: "r"(sa), "l"(g) : "memory");
            }
            asm volatile("cp.async.commit_group;" ::: "memory");
        };

        issue(0);
        issue(1);
        for (int c = 0; c < 8; c++) {
            if (c < 7)
                asm volatile("cp.async.wait_group 1;" ::: "memory");
            else
                asm volatile("cp.async.wait_group 0;" ::: "memory");
            __syncthreads();
            if (c + 2 < 8) issue(c + 2);
            unsigned stage = base + 1024 + (unsigned)(c % 3) * STAGE_SZ;
            unsigned sAh = stage, sAl = stage + 16384, sBh = stage + 32768, sBl = stage + 49152;
#pragma unroll
            for (int kk = 0; kk < 4; kk++) {
                unsigned ca = (a_c0 + (unsigned)(kk * 32)) ^ msk;
                unsigned cb = (b_c0 + (unsigned)(kk * 32)) ^ msk;
                unsigned ah[2][4], al[2][4], bh[2][4], bl[2][4];
#pragma unroll
                for (int mt = 0; mt < 2; mt++) {
                    ldm4(ah[mt], sAh + a_row[mt] + ca);
                    ldm4(al[mt], sAl + a_row[mt] + ca);
                }
#pragma unroll
                for (int np = 0; np < 2; np++) {
                    ldm4(bh[np], sBh + b_row[np] + cb);
                    ldm4(bl[np], sBl + b_row[np] + cb);
                }
#pragma unroll
                for (int mt = 0; mt < 2; mt++)
#pragma unroll
                    for (int nt = 0; nt < 4; nt++)
                        mma_bf16(acc[mt][nt], ah[mt], &bh[nt >> 1][(nt & 1) * 2]);
#pragma unroll
                for (int mt = 0; mt < 2; mt++)
#pragma unroll
                    for (int nt = 0; nt < 4; nt++)
                        mma_bf16(acc[mt][nt], ah[mt], &bl[nt >> 1][(nt & 1) * 2]);
#pragma unroll
                for (int mt = 0; mt < 2; mt++)
#pragma unroll
                    for (int nt = 0; nt < 4; nt++)
                        mma_bf16(acc[mt][nt], al[mt], &bh[nt >> 1][(nt & 1) * 2]);
            }
        }

#pragma unroll
        for (int mt = 0; mt < 2; mt++) {
#pragma unroll
            for (int nt = 0; nt < 4; nt++) {
                int r0 = wm + mt * 16 + (lane >> 2);
                int c0 = wn + nt * 8 + (lane & 3) * 2;
                float v0 = acc[mt][nt][0], v1 = acc[mt][nt][1];
                float v2 = acc[mt][nt][2], v3 = acc[mt][nt][3];
                C[r0 * KK + c0] = v0;
                C[r0 * KK + c0 + 1] = v1;
                C[(r0 + 8) * KK + c0] = v2;
                C[(r0 + 8) * KK + c0 + 1] = v3;
                CT[c0 * KK + r0] = v0;
                CT[(c0 + 1) * KK + r0] = v1;
                CT[c0 * KK + r0 + 8] = v2;
                CT[(c0 + 1) * KK + r0 + 8] = v3;
            }
        }
        return;
    }

    // ----- inversion (id < 32) -----
    float* M  = sm;
    float* Cs = sm + 128 * MST;
    float* T  = Cs + 128 * CST;
    const float* S = g_S + (size_t)id * KK * KK;
    float* Si = g_Sinv + (size_t)id * KK * KK;
    int tx = tid & 15, ty = tid >> 4;

#pragma unroll
    for (int u = 0; u < 8; u++) {
        int v = tid + u * 512;
        int m = v >> 5, c4 = (v & 31) << 2;
        *(float4*)(M + m * MST + c4) = *(const float4*)(S + m * 128 + c4);
    }
    __syncthreads();

    for (int p = 0; p < 4; p++) {
        int p0 = p * 32;
#pragma unroll
        for (int u = 0; u < 2; u++) {
            int v = tid + u * 512;
            int i = v >> 3, q4 = (v & 7) << 2;
            *(float4*)(Cs + i * CST + q4) = *(const float4*)(M + i * MST + p0 + q4);
        }
        __syncthreads();

        if (tid < 32) {
            float reg[32];
#pragma unroll
            for (int i = 0; i < 32; i++)
                reg[i] = M[(p0 + i) * MST + p0 + lane];
#pragma unroll
            for (int j = 0; j < 32; j++) {
                float piv = __shfl_sync(0xffffffffu, reg[j], j);
                float pivinv = 1.0f / piv;
                float rowj = (lane == j) ? pivinv : reg[j] * pivinv;
#pragma unroll
                for (int i = 0; i < 32; i++) {
                    if (i == j) continue;
                    float f = __shfl_sync(0xffffffffu, reg[i], j);
                    reg[i] = (lane == j) ? (-f * pivinv) : fmaf(-f, rowj, reg[i]);
                }
                reg[j] = rowj;
            }
#pragma unroll
            for (int i = 0; i < 32; i++)
                T[i * TST + lane] = reg[i];
        }
        __syncthreads();

        {
            int qr = ty;
            int cb = tx * 8;
            float out[8];
#pragma unroll
            for (int a = 0; a < 8; a++) out[a] = 0.0f;
            for (int r = 0; r < 32; r++) {
                float tq = T[qr * TST + r];
                const float* Mr = M + (p0 + r) * MST + cb;
#pragma unroll
                for (int a = 0; a < 8; a += 4) {
                    float4 mv = *(const float4*)(Mr + a);
                    out[a + 0] += tq * mv.x;
                    out[a + 1] += tq * mv.y;
                    out[a + 2] += tq * mv.z;
                    out[a + 3] += tq * mv.w;
                }
            }
            __syncthreads();
#pragma unroll
            for (int a = 0; a < 8; a++) {
                int l = cb + a;
                float vv = (l >= p0 && l < p0 + 32) ? T[qr * TST + (l - p0)] : out[a];
                M[(p0 + qr) * MST + l] = vv;
            }
            __syncthreads();
        }

        {
            ull acc2[3][4];
#pragma unroll
            for (int r = 0; r < 3; r++)
#pragma unroll
                for (int c = 0; c < 4; c++) acc2[r][c] = 0ULL;
            for (int q = 0; q < 32; q++) {
                const float* Mp = M + (p0 + q) * MST + tx * 8;
                ull b0 = *(const ull*)(Mp + 0);
                ull b1 = *(const ull*)(Mp + 2);
                ull b2 = *(const ull*)(Mp + 4);
                ull b3 = *(const ull*)(Mp + 6);
#pragma unroll
                for (int r = 0; r < 3; r++) {
                    int z = ty + 32 * r;
                    int i = (z < p0) ? z : z + 32;
                    float av = Cs[i * CST + q];
                    ull a2 = pack2(av, av);
                    ffma2(acc2[r][0], a2, b0);
                    ffma2(acc2[r][1], a2, b1);
                    ffma2(acc2[r][2], a2, b2);
                    ffma2(acc2[r][3], a2, b3);
                }
            }
#pragma unroll
            for (int r = 0; r < 3; r++) {
                int z = ty + 32 * r;
                int i = (z < p0) ? z : z + 32;
#pragma unroll
                for (int c = 0; c < 4; c++) {
                    int l = tx * 8 + 2 * c;
                    float lo, hi;
                    unpack2(acc2[r][c], lo, hi);
                    float* Mp = M + i * MST + l;
                    bool inP0 = (l >= p0 && l < p0 + 32);
                    bool inP1 = (l + 1 >= p0 && l + 1 < p0 + 32);
                    float o0 = (inP0 ? 0.0f : Mp[0]) - lo;
                    float o1 = (inP1 ? 0.0f : Mp[1]) - hi;
                    Mp[0] = o0;
                    Mp[1] = o1;
                }
            }
            __syncthreads();
        }
    }

#pragma unroll
    for (int u = 0; u < 8; u++) {
        int v = tid + u * 512;
        int m = v >> 5, c4 = (v & 31) << 2;
        *(float4*)(Si + m * 128 + c4) = *(const float4*)(M + m * MST + c4);
    }
}

// ---------------------------------------------------------------------------
// solve_hmma v3: mask/D computed in-kernel (overlapped with Sinv load).
// smem: X fp32 64K (XOR-swz) | S tiles 64K | T tiles 64K | D bf16 32K.
// Mask scratch lives at the start of the T region (overwritten by conv R later).
// ---------------------------------------------------------------------------
#define SOLVE_SMEM (1024 + 3 * 65536 + 32768)

__device__ __forceinline__ unsigned XSWZ(int row, unsigned cb) {
    return (unsigned)row * 512u + (cb ^ (unsigned)((row & 31) << 4));
}
__device__ __forceinline__ unsigned DSWZ(int row, unsigned cb) {
    return (unsigned)row * 256u + (cb ^ (unsigned)((row & 15) << 4));
}

__device__ __forceinline__ void conv_store8(const float* f, unsigned th, unsigned tl,
                                            unsigned off) {
    unsigned hw[4], lw[4];
#pragma unroll
    for (int w2 = 0; w2 < 4; w2++) {
        unsigned short h0, l0, h1, l1;
        split1(f[2 * w2], h0, l0); split1(f[2 * w2 + 1], h1, l1);
        hw[w2] = (unsigned)h0 | ((unsigned)h1 << 16);
        lw[w2] = (unsigned)l0 | ((unsigned)l1 << 16);
    }
    sts128(th + off, hw[0], hw[1], hw[2], hw[3]);
    sts128(tl + off, lw[0], lw[1], lw[2], lw[3]);
}

__device__ __forceinline__ void solve_K128(unsigned sT, unsigned sS,
                                           const unsigned* a_row, const unsigned* b_row,
                                           unsigned a_c0, unsigned b_c0, unsigned msk,
                                           float acc[4][4][4]) {
#pragma unroll
    for (int mt = 0; mt < 4; mt++)
#pragma unroll
        for (int nt = 0; nt < 4; nt++)
#pragma unroll
            for (int i = 0; i < 4; i++) acc[mt][nt][i] = 0.0f;
#pragma unroll
    for (int kc = 0; kc < 2; kc++) {
        unsigned tTh = sT + (unsigned)kc * 32768u, tTl = tTh + 16384u;
        unsigned tSh = sS + (unsigned)kc * 32768u, tSl = tSh + 16384u;
#pragma unroll
        for (int kk = 0; kk < 4; kk++) {
            unsigned ca = (a_c0 + (unsigned)(kk * 32)) ^ msk;
            unsigned cb = (b_c0 + (unsigned)(kk * 32)) ^ msk;
            unsigned ah[4][4], al[4][4], bh[2][4], bl[2][4];
#pragma unroll
            for (int mt = 0; mt < 4; mt++) {
                ldm4(ah[mt], tTh + a_row[mt] + ca);
                ldm4(al[mt], tTl + a_row[mt] + ca);
            }
#pragma unroll
            for (int np = 0; np < 2; np++) {
                ldm4(bh[np], tSh + b_row[np] + cb);
                ldm4(bl[np], tSl + b_row[np] + cb);
            }
#pragma unroll
            for (int mt = 0; mt < 4; mt++)
#pragma unroll
                for (int nt = 0; nt < 4; nt++)
                    mma_bf16(acc[mt][nt], ah[mt], &bh[nt >> 1][(nt & 1) * 2]);
#pragma unroll
            for (int mt = 0; mt < 4; mt++)
#pragma unroll
                for (int nt = 0; nt < 4; nt++)
                    mma_bf16(acc[mt][nt], ah[mt], &bl[nt >> 1][(nt & 1) * 2]);
#pragma unroll
            for (int mt = 0; mt < 4; mt++)
#pragma unroll
                for (int nt = 0; nt < 4; nt++)
                    mma_bf16(acc[mt][nt], al[mt], &bh[nt >> 1][(nt & 1) * 2]);
        }
    }
}

__global__ void __launch_bounds__(256, 1)
solve_hmma(float* __restrict__ out,
           const float* __restrict__ evx, const float* __restrict__ evy,
           const float* __restrict__ ax,  const float* __restrict__ ay) {
    extern __shared__ char smraw[];
    unsigned base = (smem_u32(smraw) + 1023) & ~1023u;
    char* alignedp = smraw + (base - smem_u32(smraw));
    unsigned sX  = base;
    unsigned sS  = base + 65536;
    unsigned sT  = base + 131072;
    unsigned sDb = base + 196608;
    int id = blockIdx.x;
    int b = id >> 1, dir = id & 1;
    const float* Sinv = g_Sinv + (size_t)id * KK * KK;
    const float* Rb = (dir ? g_RT : g_R) + (size_t)b * KK * KK;
    float* Cout = out + (size_t)(dir ? BB * KK * KK : 0) + (size_t)b * KK * KK;
    int tid = threadIdx.x, wid = tid >> 5, lane = tid & 31;

    int wm = (wid & 1) * 64, wn = (wid >> 1) * 32;
    unsigned msk = (unsigned)((lane & 7) << 4);
    unsigned a_c0 = (unsigned)((lane >> 4) * 16);
    unsigned b_c0 = (unsigned)(((lane >> 3) & 1) * 16);
    unsigned a_row[4], b_row[2];
#pragma unroll
    for (int mt = 0; mt < 4; mt++)
        a_row[mt] = (unsigned)((wm + mt * 16 + (lane & 15)) * 128);
#pragma unroll
    for (int np = 0; np < 2; np++)
        b_row[np] = (unsigned)((wn + np * 16 + ((lane >> 4) << 3) + (lane & 7)) * 128);

    int crow = tid & 127, ckc = tid >> 7;
    unsigned convTh = sT + (unsigned)ckc * 32768u, convTl = convTh + 16384u;
    unsigned convSh = sS + (unsigned)ckc * 32768u, convSl = convSh + 16384u;

    // issue Sinv -> X (overlaps with mask/D computation below)
#pragma unroll
    for (int u = 0; u < 16; u++) {
        int v = tid + u * 256;
        int row = v >> 5, seg = v & 31;
        asm volatile("cp.async.cg.shared.global [%0], [%1], 16;"
                     :: "r"(sX + XSWZ(row, (unsigned)(seg * 16))),
                        "l"((const float4*)Sinv + v) : "memory");
    }
    asm volatile("cp.async.commit_group;" ::: "memory");

    // ===== mask -> D (bf16, into sDb). Scratch lives in T region. =====
    {
        float* MK = (float*)(alignedp + 131072);
        float* t1 = MK;        float* u1 = MK + 128;
        float* t2 = MK + 256;  float* u2 = MK + 384;
        float* v1 = MK + 512;  float* w1 = MK + 640;
        float* v2 = MK + 768;  float* w2 = MK + 896;
        float* red = MK + 1024;
        float* scp = MK + 1152;   // [0]=sc_main, [1]=sc_aux

        const float* e1p = (dir ? evy : evx) + b * KK;
        const float* e2p = (dir ? evx : evy) + b * KK;
        const float* a1p = (dir ? ay : ax) + b * KK;
        const float* a2p = (dir ? ax : ay) + b * KK;

        float e1 = 0.f, e2 = 0.f, q1 = 0.f, q2 = 0.f;
        if (tid < 128) {
            e1 = fmaxf(e1p[tid], 1e-10f);
            e2 = fmaxf(e2p[tid], 1e-10f);
            q1 = fmaxf(a1p[tid], 1e-10f);
            q2 = fmaxf(a2p[tid], 1e-10f);
            red[tid] = fmaxf(e1, e2);
        }
        __syncthreads();
        for (int off = 64; off; off >>= 1) {
            if (tid < off) red[tid] = fmaxf(red[tid], red[tid + off]);
            __syncthreads();
        }
        if (tid == 0) scp[0] = fmaxf(red[0], 1e-10f);
        __syncthreads();
        if (tid < 128) red[tid] = fmaxf(q1, q2);
        __syncthreads();
        for (int off = 64; off; off >>= 1) {
            if (tid < off) red[tid] = fmaxf(red[tid], red[tid + off]);
            __syncthreads();
        }
        if (tid == 0) scp[1] = fmaxf(red[0], 1e-10f);
        __syncthreads();

        if (tid < 128) {
            float sc_main = scp[0], sc_aux = scp[1];
            float r, d;
            r = e1 / sc_main; d = r + 1.0f; t1[tid] = sqrtf(r) / d; u1[tid] = 1.0f / d;
            r = e2 / sc_main; d = r + 1.0f; t2[tid] = sqrtf(r) / d; u2[tid] = 1.0f / d;
            r = q1 / sc_aux;  d = r + 1.0f; v1[tid] = sqrtf(r) / d; w1[tid] = 1.0f / d;
            r = q2 / sc_aux;  d = r + 1.0f; v2[tid] = sqrtf(r) / d; w2[tid] = 1.0f / d;
        }
        __syncthreads();

        // D generation: 2048 16B-chunks (8 bf16 each)
        for (int v = tid; v < 2048; v += 256) {
            int i = v >> 4;
            int jb = (v & 15) << 3;
            unsigned wds[4];
#pragma unroll
            for (int q = 0; q < 4; q++) {
                float dv[2];
#pragma unroll
                for (int e = 0; e < 2; e++) {
                    int j = jb + q * 2 + e;
                    float mr = t2[i] - t1[j], mi = u2[i] - u1[j];
                    float ar = v2[i] - v1[j], ai = w2[i] - w1[j];
                    dv[e] = 100.0f * (mr * mr + mi * mi) + 25.0f * (ar * ar + ai * ai);
                }
                unsigned short b0 = __bfloat16_as_ushort(__float2bfloat16(dv[0]));
                unsigned short b1 = __bfloat16_as_ushort(__float2bfloat16(dv[1]));
                wds[q] = (unsigned)b0 | ((unsigned)b1 << 16);
            }
            sts128(sDb + DSWZ(i, (unsigned)((v & 15) * 16)), wds[0], wds[1], wds[2], wds[3]);
        }
    }

    asm volatile("cp.async.wait_group 0;" ::: "memory");
    __syncthreads();

    // conv Sinv -> S tiles (symmetry: row n serves as K-major column n)
#pragma unroll
    for (int s = 0; s < 8; s++) {
        unsigned cb = (unsigned)(ckc * 256 + s * 32);
        float4 fa = lds_f128(sX + XSWZ(crow, cb));
        float4 fb = lds_f128(sX + XSWZ(crow, cb + 16));
        float f[8] = {fa.x, fa.y, fa.z, fa.w, fb.x, fb.y, fb.z, fb.w};
        conv_store8(f, convSh, convSl, SWZ((unsigned)(crow * 128 + s * 16)));
    }
    __syncthreads();

    // load R -> X
#pragma unroll
    for (int u = 0; u < 16; u++) {
        int v = tid + u * 256;
        int row = v >> 5, seg = v & 31;
        asm volatile("cp.async.cg.shared.global [%0], [%1], 16;"
                     :: "r"(sX + XSWZ(row, (unsigned)(seg * 16))),
                        "l"((const float4*)Rb + v) : "memory");
    }
    asm volatile("cp.async.commit_group;" ::: "memory");
    asm volatile("cp.async.wait_group 0;" ::: "memory");
    __syncthreads();

    // conv R -> T tiles (overwrites mask scratch; D already materialized)
#pragma unroll
    for (int s = 0; s < 8; s++) {
        unsigned cb = (unsigned)(ckc * 256 + s * 32);
        float4 fa = lds_f128(sX + XSWZ(crow, cb));
        float4 fb = lds_f128(sX + XSWZ(crow, cb + 16));
        float f[8] = {fa.x, fa.y, fa.z, fa.w, fb.x, fb.y, fb.z, fb.w};
        conv_store8(f, convTh, convTl, SWZ((unsigned)(crow * 128 + s * 16)));
    }
    __syncthreads();

    float acc0[4][4][4], acc[4][4][4];

    // pass 0: X0 = R * Sinv (acc0 stays in registers)
    solve_K128(sT, sS, a_row, b_row, a_c0, b_c0, msk, acc0);
    __syncthreads();
#pragma unroll
    for (int mt = 0; mt < 4; mt++) {
#pragma unroll
        for (int nt = 0; nt < 4; nt++) {
            int r0 = wm + mt * 16 + (lane >> 2);
            int c0 = wn + nt * 8 + (lane & 3) * 2;
            sts_v2f(sX + XSWZ(r0, (unsigned)(c0 * 4)), acc0[mt][nt][0], acc0[mt][nt][1]);
            sts_v2f(sX + XSWZ(r0 + 8, (unsigned)(c0 * 4)), acc0[mt][nt][2], acc0[mt][nt][3]);
        }
    }
    __syncthreads();

#pragma unroll 1
    for (int pass = 1; pass <= 2; pass++) {
#pragma unroll
        for (int s = 0; s < 8; s++) {
            unsigned cb = (unsigned)(ckc * 256 + s * 32);
            float4 fa = lds_f128(sX + XSWZ(crow, cb));
            float4 fb = lds_f128(sX + XSWZ(crow, cb + 16));
            uint4 dw = lds_u128(sDb + DSWZ(crow, (unsigned)(ckc * 128 + s * 16)));
            float f[8];
            f[0] = fa.x * bf2f((unsigned short)(dw.x & 0xffff));
            f[1] = fa.y * bf2f((unsigned short)(dw.x >> 16));
            f[2] = fa.z * bf2f((unsigned short)(dw.y & 0xffff));
            f[3] = fa.w * bf2f((unsigned short)(dw.y >> 16));
            f[4] = fb.x * bf2f((unsigned short)(dw.z & 0xffff));
            f[5] = fb.y * bf2f((unsigned short)(dw.z >> 16));
            f[6] = fb.z * bf2f((unsigned short)(dw.w & 0xffff));
            f[7] = fb.w * bf2f((unsigned short)(dw.w >> 16));
            conv_store8(f, convTh, convTl, SWZ((unsigned)(crow * 128 + s * 16)));
        }
        __syncthreads();
        solve_K128(sT, sS, a_row, b_row, a_c0, b_c0, msk, acc);
        if (pass == 1) {
            __syncthreads();
#pragma unroll
            for (int mt = 0; mt < 4; mt++) {
#pragma unroll
                for (int nt = 0; nt < 4; nt++) {
                    int r0 = wm + mt * 16 + (lane >> 2);
                    int c0 = wn + nt * 8 + (lane & 3) * 2;
                    sts_v2f(sX + XSWZ(r0, (unsigned)(c0 * 4)),
                            acc0[mt][nt][0] - acc[mt][nt][0],
                            acc0[mt][nt][1] - acc[mt][nt][1]);
                    sts_v2f(sX + XSWZ(r0 + 8, (unsigned)(c0 * 4)),
                            acc0[mt][nt][2] - acc[mt][nt][2],
                            acc0[mt][nt][3] - acc[mt][nt][3]);
                }
            }
            __syncthreads();
        } else {
#pragma unroll
            for (int mt = 0; mt < 4; mt++) {
#pragma unroll
                for (int nt = 0; nt < 4; nt++) {
                    int r0 = wm + mt * 16 + (lane >> 2);
                    int c0 = wn + nt * 8 + (lane & 3) * 2;
                    *(float2*)&Cout[r0 * 128 + c0] =
                        make_float2(acc0[mt][nt][0] - acc[mt][nt][0],
                                    acc0[mt][nt][1] - acc[mt][nt][1]);
                    *(float2*)&Cout[(r0 + 8) * 128 + c0] =
                        make_float2(acc0[mt][nt][2] - acc[mt][nt][2],
                                    acc0[mt][nt][3] - acc[mt][nt][3]);
                }
            }
        }
    }
}

// ---------------------------------------------------------------------------
extern "C" void kernel_launch(void* const* d_in, const int* in_sizes, int n_in,
                              void* d_out, int out_size) {
    const float* feat_x  = (const float*)d_in[0];
    const float* feat_y  = (const float*)d_in[1];
    const float* evals_x = (const float*)d_in[2];
    const float* evals_y = (const float*)d_in[3];
    const float* evecs_x = (const float*)d_in[4];
    const float* evecs_y = (const float*)d_in[5];
    const float* aux_x   = (const float*)d_in[6];
    const float* aux_y   = (const float*)d_in[7];
    float* out = (float*)d_out;

    split_E<<<dim3(8192, 2), 256>>>(evecs_x, evecs_y);

    cudaFuncSetAttribute(mma_proj, cudaFuncAttributeMaxDynamicSharedMemorySize, MMA_SMEM);
    mma_proj<<<dim3(4, 32), 256, MMA_SMEM>>>(feat_x, feat_y);

    cudaFuncSetAttribute(gemm_nt_hmma, cudaFuncAttributeMaxDynamicSharedMemorySize, NT_SMEM);
    gemm_nt_hmma<<<32, 256, NT_SMEM>>>();

    cudaFuncSetAttribute(invert_r, cudaFuncAttributeMaxDynamicSharedMemorySize, IR_SMEM);
    invert_r<<<48, 512, IR_SMEM>>>();

    cudaFuncSetAttribute(solve_hmma, cudaFuncAttributeMaxDynamicSharedMemorySize, SOLVE_SMEM);
    solve_hmma<<<32, 256, SOLVE_SMEM>>>(out, evals_x, evals_y, aux_x, aux_y);
}

// round 16
// speedup vs baseline: 1.0890x; 1.0890x over previous
#include <cuda_runtime.h>
#include <cuda_bf16.h>

#define BB 16
#define NN 4096
#define DD 512
#define KK 128
#define REGC 1e-6f

typedef unsigned long long ull;

__device__ __forceinline__ ull pack2(float x, float y) {
    ull r; asm("mov.b64 %0, {%1, %2};" : "=l"(r) : "f"(x), "f"(y)); return r;
}
__device__ __forceinline__ void unpack2(ull v, float& lo, float& hi) {
    asm("mov.b64 {%0, %1}, %2;" : "=f"(lo), "=f"(hi) : "l"(v));
}
__device__ __forceinline__ void ffma2(ull& d, ull a, ull b) {
    asm("fma.rn.f32x2 %0, %1, %2, %0;" : "+l"(d) : "l"(a), "l"(b));
}
__device__ __forceinline__ unsigned smem_u32(const void* p) {
    unsigned a;
    asm("{ .reg .u64 t; cvta.to.shared.u64 t, %1; cvt.u32.u64 %0, t; }" : "=r"(a) : "l"(p));
    return a;
}
__device__ __forceinline__ void ldm4(unsigned* r, unsigned addr) {
    asm volatile("ldmatrix.sync.aligned.m8n8.x4.shared.b16 {%0,%1,%2,%3}, [%4];"
                 : "=r"(r[0]), "=r"(r[1]), "=r"(r[2]), "=r"(r[3]) : "r"(addr));
}
__device__ __forceinline__ void mma_bf16(float* d, const unsigned* a, const unsigned* b) {
    asm volatile(
        "mma.sync.aligned.m16n8k16.row.col.f32.bf16.bf16.f32 "
        "{%0,%1,%2,%3}, {%4,%5,%6,%7}, {%8,%9}, {%0,%1,%2,%3};"
        : "+f"(d[0]), "+f"(d[1]), "+f"(d[2]), "+f"(d[3])
        : "r"(a[0]), "r"(a[1]), "r"(a[2]), "r"(a[3]), "r"(b[0]), "r"(b[1]));
}
__device__ __forceinline__ float lds_f32(unsigned a) {
    float v; asm volatile("ld.shared.f32 %0, [%1];" : "=f"(v) : "r"(a)); return v;
}
__device__ __forceinline__ float4 lds_f128(unsigned a) {
    float4 v;
    asm volatile("ld.shared.v4.f32 {%0,%1,%2,%3}, [%4];"
                 : "=f"(v.x), "=f"(v.y), "=f"(v.z), "=f"(v.w) : "r"(a));
    return v;
}
__device__ __forceinline__ uint4 lds_u128(unsigned a) {
    uint4 v;
    asm volatile("ld.shared.v4.b32 {%0,%1,%2,%3}, [%4];"
                 : "=r"(v.x), "=r"(v.y), "=r"(v.z), "=r"(v.w) : "r"(a));
    return v;
}
__device__ __forceinline__ void sts128(unsigned a, unsigned r0, unsigned r1,
                                       unsigned r2, unsigned r3) {
    asm volatile("st.shared.v4.b32 [%0], {%1,%2,%3,%4};"
                 :: "r"(a), "r"(r0), "r"(r1), "r"(r2), "r"(r3) : "memory");
}
__device__ __forceinline__ void sts_v2f(unsigned a, float x, float y) {
    asm volatile("st.shared.v2.f32 [%0], {%1,%2};" :: "r"(a), "f"(x), "f"(y) : "memory");
}
#define SWZ(o) ((o) ^ (((o) >> 3) & 0x70))

// Scratch
__device__ float g_S[2 * BB * KK * KK];
__device__ float g_Sinv[2 * BB * KK * KK];
__device__ float g_R[BB * KK * KK];
__device__ float g_RT[BB * KK * KK];
__device__ __nv_bfloat16 g_Dbf[2 * BB * KK * KK];
__device__ __nv_bfloat16 g_Ehi[2 * BB * KK * NN];
__device__ __nv_bfloat16 g_Elo[2 * BB * KK * NN];
__device__ __nv_bfloat16 g_ABhi[2 * BB * KK * DD];
__device__ __nv_bfloat16 g_ABlo[2 * BB * KK * DD];

__device__ __forceinline__ void split1(float x, unsigned short& h, unsigned short& l) {
    __nv_bfloat16 hb = __float2bfloat16_rn(x);
    float r = x - __bfloat162float(hb);
    __nv_bfloat16 lb = __float2bfloat16_rn(r);
    h = __bfloat16_as_ushort(hb);
    l = __bfloat16_as_ushort(lb);
}
__device__ __forceinline__ float bf2f(unsigned short u) {
    return __bfloat162float(__ushort_as_bfloat16(u));
}
// fast truncation split of a pair: hw = packed hi bf16x2, lw = packed lo bf16x2
__device__ __forceinline__ void split_pair_fast(float x0, float x1,
                                                unsigned& hw, unsigned& lw) {
    unsigned u0 = __float_as_uint(x0), u1 = __float_as_uint(x1);
    hw = __byte_perm(u0, u1, 0x7632);
    float r0 = x0 - __uint_as_float(u0 & 0xffff0000u);
    float r1 = x1 - __uint_as_float(u1 & 0xffff0000u);
    __nv_bfloat162 lo2 = __float22bfloat162_rn(make_float2(r0, r1));
    lw = *(unsigned*)&lo2;
}

// ---------------------------------------------------------------------------
// split_E (unchanged)
// ---------------------------------------------------------------------------
__global__ void split_E(const float* __restrict__ ex, const float* __restrict__ ey) {
    int w = blockIdx.y;
    const float* E = w ? ey : ex;
    size_t i4 = (size_t)blockIdx.x * 256 + threadIdx.x;
    float4 t = *((const float4*)E + i4);
    unsigned short h0, h1, h2, h3, l0, l1, l2, l3;
    split1(t.x, h0, l0); split1(t.y, h1, l1); split1(t.z, h2, l2); split1(t.w, h3, l3);
    ull hp = (ull)h0 | ((ull)h1 << 16) | ((ull)h2 << 32) | ((ull)h3 << 48);
    ull lp = (ull)l0 | ((ull)l1 << 16) | ((ull)l2 << 32) | ((ull)l3 << 48);
    size_t o = (size_t)w * (BB * KK * NN) + i4 * 4;
    *(ull*)(g_Ehi + o) = hp;
    *(ull*)(g_Elo + o) = lp;
}

// ---------------------------------------------------------------------------
// mma_proj v2: pipelined conversion (conv c+1 overlaps MMA c), 1 barrier/chunk.
// smem: A stages x3 (Ah|Al 32K each) | F fp32 x2 (32K) | convB x2 (Bh|Bl 32K)
// ---------------------------------------------------------------------------
#define OFF_A  1024
#define OFF_F  (1024 + 3 * 32768)
#define OFF_CV (OFF_F + 2 * 32768)
#define MMA_SMEM (OFF_CV + 2 * 32768)   // 230400, same as before

__global__ void __launch_bounds__(256, 1) mma_proj(const float* __restrict__ fx,
                                                   const float* __restrict__ fy) {
    extern __shared__ char smraw[];
    unsigned base = (smem_u32(smraw) + 1023) & ~1023u;
    int tid = threadIdx.x, wid = tid >> 5, lane = tid & 31;

    int p = blockIdx.y; int w = p >> 4, b = p & 15;
    int n0 = blockIdx.x * 128;
    const __nv_bfloat16* Eh = g_Ehi + (size_t)p * KK * NN;
    const __nv_bfloat16* El = g_Elo + (size_t)p * KK * NN;
    const float* Ff = (w ? fy : fx) + (size_t)b * NN * DD + n0;
    size_t cbase = (size_t)p * KK * DD + n0;

    int wm = (wid & 1) * 64, wn = (wid >> 1) * 32;

    float acc[4][4][4];
#pragma unroll
    for (int mt = 0; mt < 4; mt++)
#pragma unroll
        for (int nt = 0; nt < 4; nt++)
#pragma unroll
            for (int i = 0; i < 4; i++) acc[mt][nt][i] = 0.0f;

    unsigned msk = (unsigned)((lane & 7) << 4);
    unsigned a_c0 = (unsigned)((lane >> 4) * 16);
    unsigned b_c0 = (unsigned)(((lane >> 3) & 1) * 16);
    unsigned a_row[4], b_row[2];
#pragma unroll
    for (int mt = 0; mt < 4; mt++)
        a_row[mt] = (unsigned)((wm + mt * 16 + (lane & 15)) * 128);
#pragma unroll
    for (int np = 0; np < 2; np++)
        b_row[np] = (unsigned)((wn + np * 16 + ((lane >> 4) << 3) + (lane & 7)) * 128);

    int cd = tid & 127, ckg = tid >> 7;

    auto issueAF = [&](int c) {
        unsigned astage = base + OFF_A + (unsigned)(c % 3) * 32768u;
        unsigned fstage = base + OFF_F + (unsigned)(c % 2) * 32768u;
        int k0 = c * 64;
#pragma unroll
        for (int u = 0; u < 8; u++) {
            int tile = u >> 2;
            int v = tid + (u & 3) * 256;
            int r = v >> 3, s = v & 7;
            unsigned sa = astage + tile * 16384 + SWZ((unsigned)(r * 128 + s * 16));
            const __nv_bfloat16* g = (tile ? El : Eh) + (size_t)r * NN + k0 + s * 8;
            asm volatile("cp.async.cg.shared.global [%0], [%1], 16;"
                         :: "r"(sa), "l"(g) : "memory");
        }
#pragma unroll
        for (int u = 0; u < 8; u++) {
            int v = tid + u * 256;
            int r = v >> 5, s = v & 31;
            unsigned sa = fstage + (unsigned)(r * 512 + s * 16);
            const float* g = Ff + (size_t)(k0 + r) * DD + s * 4;
            asm volatile("cp.async.cg.shared.global [%0], [%1], 16;"
                         :: "r"(sa), "l"(g) : "memory");
        }
        asm volatile("cp.async.commit_group;" ::: "memory");
    };

    auto convF = [&](int c) {
        unsigned fpb = base + OFF_F + (unsigned)(c % 2) * 32768u;
        unsigned th = base + OFF_CV + (unsigned)(c % 2) * 32768u;
        unsigned tl = th + 16384u;
#pragma unroll
        for (int kq = 0; kq < 4; kq++) {
            int kstart = ckg * 8 + kq * 16;
            unsigned hw[4], lw[4];
#pragma unroll
            for (int w2 = 0; w2 < 4; w2++) {
                float x0 = lds_f32(fpb + (unsigned)(((kstart + 2 * w2) * 128 + cd) * 4));
                float x1 = lds_f32(fpb + (unsigned)(((kstart + 2 * w2 + 1) * 128 + cd) * 4));
                split_pair_fast(x0, x1, hw[w2], lw[w2]);
            }
            unsigned off = SWZ((unsigned)(cd * 128 + kstart * 2));
            sts128(th + off, hw[0], hw[1], hw[2], hw[3]);
            sts128(tl + off, lw[0], lw[1], lw[2], lw[3]);
        }
    };

    issueAF(0);
    issueAF(1);
    asm volatile("cp.async.wait_group 1;" ::: "memory");
    __syncthreads();
    convF(0);

    for (int c = 0; c < 64; c++) {
        asm volatile("cp.async.wait_group 0;" ::: "memory");
        __syncthreads();           // conv(c) visible; frees A[(c+2)%3], F[c%2], CV[(c+1)%2]
        if (c + 2 < 64) issueAF(c + 2);
        if (c + 1 < 64) convF(c + 1);

        unsigned astage = base + OFF_A + (unsigned)(c % 3) * 32768u;
        unsigned sAh = astage, sAl = astage + 16384u;
        unsigned cvb = base + OFF_CV + (unsigned)(c % 2) * 32768u;
        unsigned sBh = cvb, sBl = cvb + 16384u;
#pragma unroll
        for (int kk = 0; kk < 4; kk++) {
            unsigned ca = (a_c0 + (unsigned)(kk * 32)) ^ msk;
            unsigned cb = (b_c0 + (unsigned)(kk * 32)) ^ msk;
            unsigned ah[4][4], al[4][4], bh[2][4], bl[2][4];
#pragma unroll
            for (int mt = 0; mt < 4; mt++) {
                ldm4(ah[mt], sAh + a_row[mt] + ca);
                ldm4(al[mt], sAl + a_row[mt] + ca);
            }
#pragma unroll
            for (int np = 0; np < 2; np++) {
                ldm4(bh[np], sBh + b_row[np] + cb);
                ldm4(bl[np], sBl + b_row[np] + cb);
            }
#pragma unroll
            for (int mt = 0; mt < 4; mt++)
#pragma unroll
                for (int nt = 0; nt < 4; nt++)
                    mma_bf16(acc[mt][nt], ah[mt], &bh[nt >> 1][(nt & 1) * 2]);
#pragma unroll
            for (int mt = 0; mt < 4; mt++)
#pragma unroll
                for (int nt = 0; nt < 4; nt++)
                    mma_bf16(acc[mt][nt], ah[mt], &bl[nt >> 1][(nt & 1) * 2]);
#pragma unroll
            for (int mt = 0; mt < 4; mt++)
#pragma unroll
                for (int nt = 0; nt < 4; nt++)
                    mma_bf16(acc[mt][nt], al[mt], &bh[nt >> 1][(nt & 1) * 2]);
        }
    }

#pragma unroll
    for (int mt = 0; mt < 4; mt++) {
#pragma unroll
        for (int nt = 0; nt < 4; nt++) {
            int r0 = wm + mt * 16 + (lane >> 2);
            int c0 = wn + nt * 8 + (lane & 3) * 2;
            unsigned short h0, l0, h1, l1, h2, l2, h3, l3;
            split1(acc[mt][nt][0], h0, l0);
            split1(acc[mt][nt][1], h1, l1);
            split1(acc[mt][nt][2], h2, l2);
            split1(acc[mt][nt][3], h3, l3);
            size_t o01 = cbase + (size_t)r0 * DD + c0;
            size_t o23 = cbase + (size_t)(r0 + 8) * DD + c0;
            *(unsigned*)(g_ABhi + o01) = (unsigned)h0 | ((unsigned)h1 << 16);
            *(unsigned*)(g_ABlo + o01) = (unsigned)l0 | ((unsigned)l1 << 16);
            *(unsigned*)(g_ABhi + o23) = (unsigned)h2 | ((unsigned)h3 << 16);
            *(unsigned*)(g_ABlo + o23) = (unsigned)l2 | ((unsigned)l3 << 16);
        }
    }
}

// ---------------------------------------------------------------------------
// gemm_nt_hmma (R14: 48 CTAs, S+R; S-mode skips duplicate Q loads)
// ---------------------------------------------------------------------------
#define NTSTAGE_BYTES 65536
#define NT_SMEM (1024 + 3 * NTSTAGE_BYTES)
__global__ void __launch_bounds__(256, 1) gemm_nt_hmma() {
    extern __shared__ char smraw[];
    unsigned base = (smem_u32(smraw) + 1023) & ~1023u;
    int tid = threadIdx.x, wid = tid >> 5, lane = tid & 31;

    int id = blockIdx.x;
    int b = id / 3, mode = id % 3;
    size_t offA = (size_t)b * KK * DD;
    size_t offB = (size_t)(BB + b) * KK * DD;
    size_t offP = (mode == 0) ? offA : offB;
    size_t offQ = (mode == 1) ? offB : offA;
    const __nv_bfloat16* Ph = g_ABhi + offP;
    const __nv_bfloat16* Pl = g_ABlo + offP;
    const __nv_bfloat16* Qh = g_ABhi + offQ;
    const __nv_bfloat16* Ql = g_ABlo + offQ;
    float* C = (mode < 2) ? g_S + (size_t)(b * 2 + mode) * KK * KK
                          : g_R + (size_t)b * KK * KK;
    float* CT = g_RT + (size_t)b * KK * KK;

    int wm = (wid & 1) * 64, wn = (wid >> 1) * 32;

    float acc[4][4][4];
#pragma unroll
    for (int mt = 0; mt < 4; mt++)
#pragma unroll
        for (int nt = 0; nt < 4; nt++)
#pragma unroll
            for (int i = 0; i < 4; i++) acc[mt][nt][i] = 0.0f;

    unsigned msk = (unsigned)((lane & 7) << 4);
    unsigned a_c0 = (unsigned)((lane >> 4) * 16);
    unsigned b_c0 = (unsigned)(((lane >> 3) & 1) * 16);
    unsigned a_row[4], b_row[2];
#pragma unroll
    for (int mt = 0; mt < 4; mt++)
        a_row[mt] = (unsigned)((wm + mt * 16 + (lane & 15)) * 128);
#pragma unroll
    for (int np = 0; np < 2; np++)
        b_row[np] = (unsigned)((wn + np * 16 + ((lane >> 4) << 3) + (lane & 7)) * 128);

    auto issue = [&](int c) {
        unsigned stage = base + 1024 + (unsigned)(c % 3) * NTSTAGE_BYTES;
        int k0 = c * 64;
#pragma unroll
        for (int u = 0; u < 16; u++) {
            int tile = u >> 2;
            if (mode < 2 && tile >= 2) continue;   // S: Q == P, skip dup loads
            int v = tid + (u & 3) * 256;
            int r = v >> 3, s = v & 7;
            unsigned sa = stage + tile * 16384 + SWZ((unsigned)(r * 128 + s * 16));
            const __nv_bfloat16* g;
            if (tile == 0)      g = Ph;
            else if (tile == 1) g = Pl;
            else if (tile == 2) g = Qh;
            else                g = Ql;
            g += (size_t)r * DD + k0 + s * 8;
            asm volatile("cp.async.cg.shared.global [%0], [%1], 16;"
                         :: "r"(sa), "l"(g) : "memory");
        }
        asm volatile("cp.async.commit_group;" ::: "memory");
    };

    issue(0);
    issue(1);
    for (int c = 0; c < 8; c++) {
        if (c < 7)
            asm volatile("cp.async.wait_group 1;" ::: "memory");
        else
            asm volatile("cp.async.wait_group 0;" ::: "memory");
        __syncthreads();
        if (c + 2 < 8) issue(c + 2);
        unsigned stage = base + 1024 + (unsigned)(c % 3) * NTSTAGE_BYTES;
        unsigned sAh = stage, sAl = stage + 16384;
        unsigned sBh = (mode < 2) ? sAh : stage + 32768;
        unsigned sBl = (mode < 2) ? sAl : stage + 49152;
#pragma unroll
        for (int kk = 0; kk < 4; kk++) {
            unsigned ca = (a_c0 + (unsigned)(kk * 32)) ^ msk;
            unsigned cb = (b_c0 + (unsigned)(kk * 32)) ^ msk;
            unsigned ah[4][4], al[4][4], bh[2][4], bl[2][4];
#pragma unroll
            for (int mt = 0; mt < 4; mt++) {
                ldm4(ah[mt], sAh + a_row[mt] + ca);
                ldm4(al[mt], sAl + a_row[mt] + ca);
            }
#pragma unroll
            for (int np = 0; np < 2; np++) {
                ldm4(bh[np], sBh + b_row[np] + cb);
                ldm4(bl[np], sBl + b_row[np] + cb);
            }
#pragma unroll
            for (int mt = 0; mt < 4; mt++)
#pragma unroll
                for (int nt = 0; nt < 4; nt++)
                    mma_bf16(acc[mt][nt], ah[mt], &bh[nt >> 1][(nt & 1) * 2]);
#pragma unroll
            for (int mt = 0; mt < 4; mt++)
#pragma unroll
                for (int nt = 0; nt < 4; nt++)
                    mma_bf16(acc[mt][nt], ah[mt], &bl[nt >> 1][(nt & 1) * 2]);
#pragma unroll
            for (int mt = 0; mt < 4; mt++)
#pragma unroll
                for (int nt = 0; nt < 4; nt++)
                    mma_bf16(acc[mt][nt], al[mt], &bh[nt >> 1][(nt & 1) * 2]);
        }
    }

#pragma unroll
    for (int mt = 0; mt < 4; mt++) {
#pragma unroll
        for (int nt = 0; nt < 4; nt++) {
            int r0 = wm + mt * 16 + (lane >> 2);
            int c0 = wn + nt * 8 + (lane & 3) * 2;
            float v0 = acc[mt][nt][0], v1 = acc[mt][nt][1];
            float v2 = acc[mt][nt][2], v3 = acc[mt][nt][3];
            if (mode < 2) {
                if (r0 == c0) v0 += REGC;
                if (r0 == c0 + 1) v1 += REGC;
                if (r0 + 8 == c0) v2 += REGC;
                if (r0 + 8 == c0 + 1) v3 += REGC;
            }
            C[r0 * KK + c0] = v0;
            C[r0 * KK + c0 + 1] = v1;
            C[(r0 + 8) * KK + c0] = v2;
            C[(r0 + 8) * KK + c0 + 1] = v3;
            if (mode == 2) {
                CT[c0 * KK + r0] = v0;
                CT[(c0 + 1) * KK + r0] = v1;
                CT[c0 * KK + r0 + 8] = v2;
                CT[(c0 + 1) * KK + r0 + 8] = v3;
            }
        }
    }
}

// ---------------------------------------------------------------------------
// invert_mask (R14: mask writes bf16 D, blocked GJ inversion)
// ---------------------------------------------------------------------------
#define MST 132
#define CST 36
#define TST 36
#define INV_SMEM ((128 * MST + 128 * CST + 32 * TST) * 4)

__global__ void __launch_bounds__(512, 1)
invert_mask(const float* __restrict__ evx, const float* __restrict__ evy,
            const float* __restrict__ ax,  const float* __restrict__ ay) {
    extern __shared__ float sm[];
    float* M  = sm;
    float* Cs = sm + 128 * MST;
    float* T  = Cs + 128 * CST;
    int id = blockIdx.x;
    int b = id >> 1, dir = id & 1;
    const float* S = g_S + (size_t)id * KK * KK;
    float* Si = g_Sinv + (size_t)id * KK * KK;
    int tid = threadIdx.x;
    int lane = tid & 31;
    int tx = tid & 15, ty = tid >> 4;

    {
        __shared__ float t1[128], u1[128], t2[128], u2[128];
        __shared__ float v1[128], w1[128], v2[128], w2[128];
        __shared__ float red[128];
        __shared__ float sc_main, sc_aux;

        const float* e1p = (dir ? evy : evx) + b * KK;
        const float* e2p = (dir ? evx : evy) + b * KK;
        const float* a1p = (dir ? ay : ax) + b * KK;
        const float* a2p = (dir ? ax : ay) + b * KK;

        float e1 = 0.f, e2 = 0.f, q1 = 0.f, q2 = 0.f;
        if (tid < 128) {
            e1 = fmaxf(e1p[tid], 1e-10f);
            e2 = fmaxf(e2p[tid], 1e-10f);
            q1 = fmaxf(a1p[tid], 1e-10f);
            q2 = fmaxf(a2p[tid], 1e-10f);
            red[tid] = fmaxf(e1, e2);
        }
        __syncthreads();
        for (int off = 64; off; off >>= 1) {
            if (tid < off) red[tid] = fmaxf(red[tid], red[tid + off]);
            __syncthreads();
        }
        if (tid == 0) sc_main = fmaxf(red[0], 1e-10f);
        __syncthreads();
        if (tid < 128) red[tid] = fmaxf(q1, q2);
        __syncthreads();
        for (int off = 64; off; off >>= 1) {
            if (tid < off) red[tid] = fmaxf(red[tid], red[tid + off]);
            __syncthreads();
        }
        if (tid == 0) sc_aux = fmaxf(red[0], 1e-10f);
        __syncthreads();

        if (tid < 128) {
            float r, d;
            r = e1 / sc_main; d = r + 1.0f; t1[tid] = sqrtf(r) / d; u1[tid] = 1.0f / d;
            r = e2 / sc_main; d = r + 1.0f; t2[tid] = sqrtf(r) / d; u2[tid] = 1.0f / d;
            r = q1 / sc_aux;  d = r + 1.0f; v1[tid] = sqrtf(r) / d; w1[tid] = 1.0f / d;
            r = q2 / sc_aux;  d = r + 1.0f; v2[tid] = sqrtf(r) / d; w2[tid] = 1.0f / d;
        }
        __syncthreads();

        __nv_bfloat16* Dp = g_Dbf + (size_t)id * (KK * KK);
        for (int v = tid; v < KK * KK; v += 512) {
            int i = v >> 7, j = v & 127;
            float mr = t2[i] - t1[j], mi = u2[i] - u1[j];
            float ar = v2[i] - v1[j], ai = w2[i] - w1[j];
            Dp[v] = __float2bfloat16(100.0f * (mr * mr + mi * mi)
                                   + 25.0f * (ar * ar + ai * ai));
        }
    }

#pragma unroll
    for (int u = 0; u < 8; u++) {
        int v = tid + u * 512;
        int m = v >> 5, c4 = (v & 31) << 2;
        *(float4*)(M + m * MST + c4) = *(const float4*)(S + m * 128 + c4);
    }
    __syncthreads();

    for (int p = 0; p < 4; p++) {
        int p0 = p * 32;
#pragma unroll
        for (int u = 0; u < 2; u++) {
            int v = tid + u * 512;
            int i = v >> 3, q4 = (v & 7) << 2;
            *(float4*)(Cs + i * CST + q4) = *(const float4*)(M + i * MST + p0 + q4);
        }
        __syncthreads();

        if (tid < 32) {
            float reg[32];
#pragma unroll
            for (int i = 0; i < 32; i++)
                reg[i] = M[(p0 + i) * MST + p0 + lane];
#pragma unroll
            for (int j = 0; j < 32; j++) {
                float piv = __shfl_sync(0xffffffffu, reg[j], j);
                float pivinv = 1.0f / piv;
                float rowj = (lane == j) ? pivinv : reg[j] * pivinv;
#pragma unroll
                for (int i = 0; i < 32; i++) {
                    if (i == j) continue;
                    float f = __shfl_sync(0xffffffffu, reg[i], j);
                    reg[i] = (lane == j) ? (-f * pivinv) : fmaf(-f, rowj, reg[i]);
                }
                reg[j] = rowj;
            }
#pragma unroll
            for (int i = 0; i < 32; i++)
                T[i * TST + lane] = reg[i];
        }
        __syncthreads();

        {
            int qr = ty;
            int cb = tx * 8;
            float out[8];
#pragma unroll
            for (int a = 0; a < 8; a++) out[a] = 0.0f;
            for (int r = 0; r < 32; r++) {
                float tq = T[qr * TST + r];
                const float* Mr = M + (p0 + r) * MST + cb;
#pragma unroll
                for (int a = 0; a < 8; a += 4) {
                    float4 mv = *(const float4*)(Mr + a);
                    out[a + 0] += tq * mv.x;
                    out[a + 1] += tq * mv.y;
                    out[a + 2] += tq * mv.z;
                    out[a + 3] += tq * mv.w;
                }
            }
            __syncthreads();
#pragma unroll
            for (int a = 0; a < 8; a++) {
                int l = cb + a;
                float vv = (l >= p0 && l < p0 + 32) ? T[qr * TST + (l - p0)] : out[a];
                M[(p0 + qr) * MST + l] = vv;
            }
            __syncthreads();
        }

        {
            ull acc2[3][4];
#pragma unroll
            for (int r = 0; r < 3; r++)
#pragma unroll
                for (int c = 0; c < 4; c++) acc2[r][c] = 0ULL;
            for (int q = 0; q < 32; q++) {
                const float* Mp = M + (p0 + q) * MST + tx * 8;
                ull b0 = *(const ull*)(Mp + 0);
                ull b1 = *(const ull*)(Mp + 2);
                ull b2 = *(const ull*)(Mp + 4);
                ull b3 = *(const ull*)(Mp + 6);
#pragma unroll
                for (int r = 0; r < 3; r++) {
                    int z = ty + 32 * r;
                    int i = (z < p0) ? z : z + 32;
                    float av = Cs[i * CST + q];
                    ull a2 = pack2(av, av);
                    ffma2(acc2[r][0], a2, b0);
                    ffma2(acc2[r][1], a2, b1);
                    ffma2(acc2[r][2], a2, b2);
                    ffma2(acc2[r][3], a2, b3);
                }
            }
#pragma unroll
            for (int r = 0; r < 3; r++) {
                int z = ty + 32 * r;
                int i = (z < p0) ? z : z + 32;
#pragma unroll
                for (int c = 0; c < 4; c++) {
                    int l = tx * 8 + 2 * c;
                    float lo, hi;
                    unpack2(acc2[r][c], lo, hi);
                    float* Mp = M + i * MST + l;
                    bool inP0 = (l >= p0 && l < p0 + 32);
                    bool inP1 = (l + 1 >= p0 && l + 1 < p0 + 32);
                    float o0 = (inP0 ? 0.0f : Mp[0]) - lo;
                    float o1 = (inP1 ? 0.0f : Mp[1]) - hi;
                    Mp[0] = o0;
                    Mp[1] = o1;
                }
            }
            __syncthreads();
        }
    }

#pragma unroll
    for (int u = 0; u < 8; u++) {
        int v = tid + u * 512;
        int m = v >> 5, c4 = (v & 31) << 2;
        *(float4*)(Si + m * 128 + c4) = *(const float4*)(M + m * MST + c4);
    }
}

// ---------------------------------------------------------------------------
// solve_hmma (R14 version)
// ---------------------------------------------------------------------------
#define SOLVE_SMEM (1024 + 3 * 65536 + 32768)

__device__ __forceinline__ unsigned XSWZ(int row, unsigned cb) {
    return (unsigned)row * 512u + (cb ^ (unsigned)((row & 31) << 4));
}
__device__ __forceinline__ unsigned DSWZ(int row, unsigned cb) {
    return (unsigned)row * 256u + (cb ^ (unsigned)((row & 15) << 4));
}

__device__ __forceinline__ void conv_store8(const float* f, unsigned th, unsigned tl,
                                            unsigned off) {
    unsigned hw[4], lw[4];
#pragma unroll
    for (int w2 = 0; w2 < 4; w2++) {
        unsigned short h0, l0, h1, l1;
        split1(f[2 * w2], h0, l0); split1(f[2 * w2 + 1], h1, l1);
        hw[w2] = (unsigned)h0 | ((unsigned)h1 << 16);
        lw[w2] = (unsigned)l0 | ((unsigned)l1 << 16);
    }
    sts128(th + off, hw[0], hw[1], hw[2], hw[3]);
    sts128(tl + off, lw[0], lw[1], lw[2], lw[3]);
}

__device__ __forceinline__ void solve_K128(unsigned sT, unsigned sS,
                                           const unsigned* a_row, const unsigned* b_row,
                                           unsigned a_c0, unsigned b_c0, unsigned msk,
                                           float acc[4][4][4]) {
#pragma unroll
    for (int mt = 0; mt < 4; mt++)
#pragma unroll
        for (int nt = 0; nt < 4; nt++)
#pragma unroll
            for (int i = 0; i < 4; i++) acc[mt][nt][i] = 0.0f;
#pragma unroll
    for (int kc = 0; kc < 2; kc++) {
        unsigned tTh = sT + (unsigned)kc * 32768u, tTl = tTh + 16384u;
        unsigned tSh = sS + (unsigned)kc * 32768u, tSl = tSh + 16384u;
#pragma unroll
        for (int kk = 0; kk < 4; kk++) {
            unsigned ca = (a_c0 + (unsigned)(kk * 32)) ^ msk;
            unsigned cb = (b_c0 + (unsigned)(kk * 32)) ^ msk;
            unsigned ah[4][4], al[4][4], bh[2][4], bl[2][4];
#pragma unroll
            for (int mt = 0; mt < 4; mt++) {
                ldm4(ah[mt], tTh + a_row[mt] + ca);
                ldm4(al[mt], tTl + a_row[mt] + ca);
            }
#pragma unroll
            for (int np = 0; np < 2; np++) {
                ldm4(bh[np], tSh + b_row[np] + cb);
                ldm4(bl[np], tSl + b_row[np] + cb);
            }
#pragma unroll
            for (int mt = 0; mt < 4; mt++)
#pragma unroll
                for (int nt = 0; nt < 4; nt++)
                    mma_bf16(acc[mt][nt], ah[mt], &bh[nt >> 1][(nt & 1) * 2]);
#pragma unroll
            for (int mt = 0; mt < 4; mt++)
#pragma unroll
                for (int nt = 0; nt < 4; nt++)
                    mma_bf16(acc[mt][nt], ah[mt], &bl[nt >> 1][(nt & 1) * 2]);
#pragma unroll
            for (int mt = 0; mt < 4; mt++)
#pragma unroll
                for (int nt = 0; nt < 4; nt++)
                    mma_bf16(acc[mt][nt], al[mt], &bh[nt >> 1][(nt & 1) * 2]);
        }
    }
}

__global__ void __launch_bounds__(256, 1) solve_hmma(float* __restrict__ out) {
    extern __shared__ char smraw[];
    unsigned base = (smem_u32(smraw) + 1023) & ~1023u;
    unsigned sX  = base;
    unsigned sS  = base + 65536;
    unsigned sT  = base + 131072;
    unsigned sDb = base + 196608;
    int id = blockIdx.x;
    int b = id >> 1, dir = id & 1;
    const float* Sinv = g_Sinv + (size_t)id * KK * KK;
    const char* Dm = (const char*)(g_Dbf + (size_t)id * KK * KK);
    const float* Rb = (dir ? g_RT : g_R) + (size_t)b * KK * KK;
    float* Cout = out + (size_t)(dir ? BB * KK * KK : 0) + (size_t)b * KK * KK;
    int tid = threadIdx.x, wid = tid >> 5, lane = tid & 31;

    int wm = (wid & 1) * 64, wn = (wid >> 1) * 32;
    unsigned msk = (unsigned)((lane & 7) << 4);
    unsigned a_c0 = (unsigned)((lane >> 4) * 16);
    unsigned b_c0 = (unsigned)(((lane >> 3) & 1) * 16);
    unsigned a_row[4], b_row[2];
#pragma unroll
    for (int mt = 0; mt < 4; mt++)
        a_row[mt] = (unsigned)((wm + mt * 16 + (lane & 15)) * 128);
#pragma unroll
    for (int np = 0; np < 2; np++)
        b_row[np] = (unsigned)((wn + np * 16 + ((lane >> 4) << 3) + (lane & 7)) * 128);

    int crow = tid & 127, ckc = tid >> 7;
    unsigned convTh = sT + (unsigned)ckc * 32768u, convTl = convTh + 16384u;
    unsigned convSh = sS + (unsigned)ckc * 32768u, convSl = convSh + 16384u;

#pragma unroll
    for (int u = 0; u < 16; u++) {
        int v = tid + u * 256;
        int row = v >> 5, seg = v & 31;
        asm volatile("cp.async.cg.shared.global [%0], [%1], 16;"
                     :: "r"(sX + XSWZ(row, (unsigned)(seg * 16))),
                        "l"((const float4*)Sinv + v) : "memory");
    }
    asm volatile("cp.async.commit_group;" ::: "memory");
#pragma unroll
    for (int u = 0; u < 8; u++) {
        int v = tid + u * 256;
        int row = v >> 4, seg = v & 15;
        asm volatile("cp.async.cg.shared.global [%0], [%1], 16;"
                     :: "r"(sDb + DSWZ(row, (unsigned)(seg * 16))),
                        "l"(Dm + (size_t)v * 16) : "memory");
    }
    asm volatile("cp.async.commit_group;" ::: "memory");
    asm volatile("cp.async.wait_group 1;" ::: "memory");
    __syncthreads();

#pragma unroll
    for (int s = 0; s < 8; s++) {
        unsigned cb = (unsigned)(ckc * 256 + s * 32);
        float4 fa = lds_f128(sX + XSWZ(crow, cb));
        float4 fb = lds_f128(sX + XSWZ(crow, cb + 16));
        float f[8] = {fa.x, fa.y, fa.z, fa.w, fb.x, fb.y, fb.z, fb.w};
        conv_store8(f, convSh, convSl, SWZ((unsigned)(crow * 128 + s * 16)));
    }
    __syncthreads();

#pragma unroll
    for (int u = 0; u < 16; u++) {
        int v = tid + u * 256;
        int row = v >> 5, seg = v & 31;
        asm volatile("cp.async.cg.shared.global [%0], [%1], 16;"
                     :: "r"(sX + XSWZ(row, (unsigned)(seg * 16))),
                        "l"((const float4*)Rb + v) : "memory");
    }
    asm volatile("cp.async.commit_group;" ::: "memory");
    asm volatile("cp.async.wait_group 0;" ::: "memory");
    __syncthreads();

#pragma unroll
    for (int s = 0; s < 8; s++) {
        unsigned cb = (unsigned)(ckc * 256 + s * 32);
        float4 fa = lds_f128(sX + XSWZ(crow, cb));
        float4 fb = lds_f128(sX + XSWZ(crow, cb + 16));
        float f[8] = {fa.x, fa.y, fa.z, fa.w, fb.x, fb.y, fb.z, fb.w};
        conv_store8(f, convTh, convTl, SWZ((unsigned)(crow * 128 + s * 16)));
    }
    __syncthreads();

    float acc0[4][4][4], acc[4][4][4];

    solve_K128(sT, sS, a_row, b_row, a_c0, b_c0, msk, acc0);
    __syncthreads();
#pragma unroll
    for (int mt = 0; mt < 4; mt++) {
#pragma unroll
        for (int nt = 0; nt < 4; nt++) {
            int r0 = wm + mt * 16 + (lane >> 2);
            int c0 = wn + nt * 8 + (lane & 3) * 2;
            sts_v2f(sX + XSWZ(r0, (unsigned)(c0 * 4)), acc0[mt][nt][0], acc0[mt][nt][1]);
            sts_v2f(sX + XSWZ(r0 + 8, (unsigned)(c0 * 4)), acc0[mt][nt][2], acc0[mt][nt][3]);
        }
    }
    __syncthreads();

#pragma unroll 1
    for (int pass = 1; pass <= 2; pass++) {
#pragma unroll
        for (int s = 0; s < 8; s++) {
            unsigned cb = (unsigned)(ckc * 256 + s * 32);
            float4 fa = lds_f128(sX + XSWZ(crow, cb));
            float4 fb = lds_f128(sX + XSWZ(crow, cb + 16));
            uint4 dw = lds_u128(sDb + DSWZ(crow, (unsigned)(ckc * 128 + s * 16)));
            float f[8];
            f[0] = fa.x * bf2f((unsigned short)(dw.x & 0xffff));
            f[1] = fa.y * bf2f((unsigned short)(dw.x >> 16));
            f[2] = fa.z * bf2f((unsigned short)(dw.y & 0xffff));
            f[3] = fa.w * bf2f((unsigned short)(dw.y >> 16));
            f[4] = fb.x * bf2f((unsigned short)(dw.z & 0xffff));
            f[5] = fb.y * bf2f((unsigned short)(dw.z >> 16));
            f[6] = fb.z * bf2f((unsigned short)(dw.w & 0xffff));
            f[7] = fb.w * bf2f((unsigned short)(dw.w >> 16));
            conv_store8(f, convTh, convTl, SWZ((unsigned)(crow * 128 + s * 16)));
        }
        __syncthreads();
        solve_K128(sT, sS, a_row, b_row, a_c0, b_c0, msk, acc);
        if (pass == 1) {
            __syncthreads();
#pragma unroll
            for (int mt = 0; mt < 4; mt++) {
#pragma unroll
                for (int nt = 0; nt < 4; nt++) {
                    int r0 = wm + mt * 16 + (lane >> 2);
                    int c0 = wn + nt * 8 + (lane & 3) * 2;
                    sts_v2f(sX + XSWZ(r0, (unsigned)(c0 * 4)),
                            acc0[mt][nt][0] - acc[mt][nt][0],
                            acc0[mt][nt][1] - acc[mt][nt][1]);
                    sts_v2f(sX + XSWZ(r0 + 8, (unsigned)(c0 * 4)),
                            acc0[mt][nt][2] - acc[mt][nt][2],
                            acc0[mt][nt][3] - acc[mt][nt][3]);
                }
            }
            __syncthreads();
        } else {
#pragma unroll
            for (int mt = 0; mt < 4; mt++) {
#pragma unroll
                for (int nt = 0; nt < 4; nt++) {
                    int r0 = wm + mt * 16 + (lane >> 2);
                    int c0 = wn + nt * 8 + (lane & 3) * 2;
                    *(float2*)&Cout[r0 * 128 + c0] =
                        make_float2(acc0[mt][nt][0] - acc[mt][nt][0],
                                    acc0[mt][nt][1] - acc[mt][nt][1]);
                    *(float2*)&Cout[(r0 + 8) * 128 + c0] =
                        make_float2(acc0[mt][nt][2] - acc[mt][nt][2],
                                    acc0[mt][nt][3] - acc[mt][nt][3]);
                }
            }
        }
    }
}

// ---------------------------------------------------------------------------
extern "C" void kernel_launch(void* const* d_in, const int* in_sizes, int n_in,
                              void* d_out, int out_size) {
    const float* feat_x  = (const float*)d_in[0];
    const float* feat_y  = (const float*)d_in[1];
    const float* evals_x = (const float*)d_in[2];
    const float* evals_y = (const float*)d_in[3];
    const float* evecs_x = (const float*)d_in[4];
    const float* evecs_y = (const float*)d_in[5];
    const float* aux_x   = (const float*)d_in[6];
    const float* aux_y   = (const float*)d_in[7];
    float* out = (float*)d_out;

    split_E<<<dim3(8192, 2), 256>>>(evecs_x, evecs_y);

    cudaFuncSetAttribute(mma_proj, cudaFuncAttributeMaxDynamicSharedMemorySize, MMA_SMEM);
    mma_proj<<<dim3(4, 32), 256, MMA_SMEM>>>(feat_x, feat_y);

    cudaFuncSetAttribute(gemm_nt_hmma, cudaFuncAttributeMaxDynamicSharedMemorySize, NT_SMEM);
    gemm_nt_hmma<<<48, 256, NT_SMEM>>>();

    cudaFuncSetAttribute(invert_mask, cudaFuncAttributeMaxDynamicSharedMemorySize, INV_SMEM);
    invert_mask<<<32, 512, INV_SMEM>>>(evals_x, evals_y, aux_x, aux_y);

    cudaFuncSetAttribute(solve_hmma, cudaFuncAttributeMaxDynamicSharedMemorySize, SOLVE_SMEM);
    solve_hmma<<<32, 256, SOLVE_SMEM>>>(out);
}

// round 17
// speedup vs baseline: 1.1061x; 1.0157x over previous
#include <cuda_runtime.h>
#include <cuda_bf16.h>

#define BB 16
#define NN 4096
#define DD 512
#define KK 128
#define REGC 1e-6f

typedef unsigned long long ull;

__device__ __forceinline__ ull pack2(float x, float y) {
    ull r; asm("mov.b64 %0, {%1, %2};" : "=l"(r) : "f"(x), "f"(y)); return r;
}
__device__ __forceinline__ void unpack2(ull v, float& lo, float& hi) {
    asm("mov.b64 {%0, %1}, %2;" : "=f"(lo), "=f"(hi) : "l"(v));
}
__device__ __forceinline__ void ffma2(ull& d, ull a, ull b) {
    asm("fma.rn.f32x2 %0, %1, %2, %0;" : "+l"(d) : "l"(a), "l"(b));
}
__device__ __forceinline__ unsigned smem_u32(const void* p) {
    unsigned a;
    asm("{ .reg .u64 t; cvta.to.shared.u64 t, %1; cvt.u32.u64 %0, t; }" : "=r"(a) : "l"(p));
    return a;
}
__device__ __forceinline__ void ldm4(unsigned* r, unsigned addr) {
    asm volatile("ldmatrix.sync.aligned.m8n8.x4.shared.b16 {%0,%1,%2,%3}, [%4];"
                 : "=r"(r[0]), "=r"(r[1]), "=r"(r[2]), "=r"(r[3]) : "r"(addr));
}
__device__ __forceinline__ void mma_bf16(float* d, const unsigned* a, const unsigned* b) {
    asm volatile(
        "mma.sync.aligned.m16n8k16.row.col.f32.bf16.bf16.f32 "
        "{%0,%1,%2,%3}, {%4,%5,%6,%7}, {%8,%9}, {%0,%1,%2,%3};"
        : "+f"(d[0]), "+f"(d[1]), "+f"(d[2]), "+f"(d[3])
        : "r"(a[0]), "r"(a[1]), "r"(a[2]), "r"(a[3]), "r"(b[0]), "r"(b[1]));
}
__device__ __forceinline__ float lds_f32(unsigned a) {
    float v; asm volatile("ld.shared.f32 %0, [%1];" : "=f"(v) : "r"(a)); return v;
}
__device__ __forceinline__ float4 lds_f128(unsigned a) {
    float4 v;
    asm volatile("ld.shared.v4.f32 {%0,%1,%2,%3}, [%4];"
                 : "=f"(v.x), "=f"(v.y), "=f"(v.z), "=f"(v.w) : "r"(a));
    return v;
}
__device__ __forceinline__ uint4 lds_u128(unsigned a) {
    uint4 v;
    asm volatile("ld.shared.v4.b32 {%0,%1,%2,%3}, [%4];"
                 : "=r"(v.x), "=r"(v.y), "=r"(v.z), "=r"(v.w) : "r"(a));
    return v;
}
__device__ __forceinline__ void sts128(unsigned a, unsigned r0, unsigned r1,
                                       unsigned r2, unsigned r3) {
    asm volatile("st.shared.v4.b32 [%0], {%1,%2,%3,%4};"
                 :: "r"(a), "r"(r0), "r"(r1), "r"(r2), "r"(r3) : "memory");
}
__device__ __forceinline__ void sts_v2f(unsigned a, float x, float y) {
    asm volatile("st.shared.v2.f32 [%0], {%1,%2};" :: "r"(a), "f"(x), "f"(y) : "memory");
}
#define SWZ(o) ((o) ^ (((o) >> 3) & 0x70))

// Scratch
__device__ float g_S[2 * BB * KK * KK];
__device__ float g_Sinv[2 * BB * KK * KK];
__device__ float g_R[BB * KK * KK];
__device__ float g_RT[BB * KK * KK];
__device__ __nv_bfloat16 g_Dbf[2 * BB * KK * KK];
__device__ __nv_bfloat16 g_Ehi[2 * BB * KK * NN];
__device__ __nv_bfloat16 g_Elo[2 * BB * KK * NN];
__device__ __nv_bfloat16 g_ABhi[2 * BB * KK * DD];
__device__ __nv_bfloat16 g_ABlo[2 * BB * KK * DD];

__device__ __forceinline__ void split1(float x, unsigned short& h, unsigned short& l) {
    __nv_bfloat16 hb = __float2bfloat16_rn(x);
    float r = x - __bfloat162float(hb);
    __nv_bfloat16 lb = __float2bfloat16_rn(r);
    h = __bfloat16_as_ushort(hb);
    l = __bfloat16_as_ushort(lb);
}
__device__ __forceinline__ float bf2f(unsigned short u) {
    return __bfloat162float(__ushort_as_bfloat16(u));
}
__device__ __forceinline__ void split_pair_fast(float x0, float x1,
                                                unsigned& hw, unsigned& lw) {
    unsigned u0 = __float_as_uint(x0), u1 = __float_as_uint(x1);
    hw = __byte_perm(u0, u1, 0x7632);
    float r0 = x0 - __uint_as_float(u0 & 0xffff0000u);
    float r1 = x1 - __uint_as_float(u1 & 0xffff0000u);
    __nv_bfloat162 lo2 = __float22bfloat162_rn(make_float2(r0, r1));
    lw = *(unsigned*)&lo2;
}

// ---------------------------------------------------------------------------
// split_E (unchanged)
// ---------------------------------------------------------------------------
__global__ void split_E(const float* __restrict__ ex, const float* __restrict__ ey) {
    int w = blockIdx.y;
    const float* E = w ? ey : ex;
    size_t i4 = (size_t)blockIdx.x * 256 + threadIdx.x;
    float4 t = *((const float4*)E + i4);
    unsigned short h0, h1, h2, h3, l0, l1, l2, l3;
    split1(t.x, h0, l0); split1(t.y, h1, l1); split1(t.z, h2, l2); split1(t.w, h3, l3);
    ull hp = (ull)h0 | ((ull)h1 << 16) | ((ull)h2 << 32) | ((ull)h3 << 48);
    ull lp = (ull)l0 | ((ull)l1 << 16) | ((ull)l2 << 32) | ((ull)l3 << 48);
    size_t o = (size_t)w * (BB * KK * NN) + i4 * 4;
    *(ull*)(g_Ehi + o) = hp;
    *(ull*)(g_Elo + o) = lp;
}

// ---------------------------------------------------------------------------
// mma_proj v2 (unchanged from R16)
// ---------------------------------------------------------------------------
#define OFF_A  1024
#define OFF_F  (1024 + 3 * 32768)
#define OFF_CV (OFF_F + 2 * 32768)
#define MMA_SMEM (OFF_CV + 2 * 32768)

__global__ void __launch_bounds__(256, 1) mma_proj(const float* __restrict__ fx,
                                                   const float* __restrict__ fy) {
    extern __shared__ char smraw[];
    unsigned base = (smem_u32(smraw) + 1023) & ~1023u;
    int tid = threadIdx.x, wid = tid >> 5, lane = tid & 31;

    int p = blockIdx.y; int w = p >> 4, b = p & 15;
    int n0 = blockIdx.x * 128;
    const __nv_bfloat16* Eh = g_Ehi + (size_t)p * KK * NN;
    const __nv_bfloat16* El = g_Elo + (size_t)p * KK * NN;
    const float* Ff = (w ? fy : fx) + (size_t)b * NN * DD + n0;
    size_t cbase = (size_t)p * KK * DD + n0;

    int wm = (wid & 1) * 64, wn = (wid >> 1) * 32;

    float acc[4][4][4];
#pragma unroll
    for (int mt = 0; mt < 4; mt++)
#pragma unroll
        for (int nt = 0; nt < 4; nt++)
#pragma unroll
            for (int i = 0; i < 4; i++) acc[mt][nt][i] = 0.0f;

    unsigned msk = (unsigned)((lane & 7) << 4);
    unsigned a_c0 = (unsigned)((lane >> 4) * 16);
    unsigned b_c0 = (unsigned)(((lane >> 3) & 1) * 16);
    unsigned a_row[4], b_row[2];
#pragma unroll
    for (int mt = 0; mt < 4; mt++)
        a_row[mt] = (unsigned)((wm + mt * 16 + (lane & 15)) * 128);
#pragma unroll
    for (int np = 0; np < 2; np++)
        b_row[np] = (unsigned)((wn + np * 16 + ((lane >> 4) << 3) + (lane & 7)) * 128);

    int cd = tid & 127, ckg = tid >> 7;

    auto issueAF = [&](int c) {
        unsigned astage = base + OFF_A + (unsigned)(c % 3) * 32768u;
        unsigned fstage = base + OFF_F + (unsigned)(c % 2) * 32768u;
        int k0 = c * 64;
#pragma unroll
        for (int u = 0; u < 8; u++) {
            int tile = u >> 2;
            int v = tid + (u & 3) * 256;
            int r = v >> 3, s = v & 7;
            unsigned sa = astage + tile * 16384 + SWZ((unsigned)(r * 128 + s * 16));
            const __nv_bfloat16* g = (tile ? El : Eh) + (size_t)r * NN + k0 + s * 8;
            asm volatile("cp.async.cg.shared.global [%0], [%1], 16;"
                         :: "r"(sa), "l"(g) : "memory");
        }
#pragma unroll
        for (int u = 0; u < 8; u++) {
            int v = tid + u * 256;
            int r = v >> 5, s = v & 31;
            unsigned sa = fstage + (unsigned)(r * 512 + s * 16);
            const float* g = Ff + (size_t)(k0 + r) * DD + s * 4;
            asm volatile("cp.async.cg.shared.global [%0], [%1], 16;"
                         :: "r"(sa), "l"(g) : "memory");
        }
        asm volatile("cp.async.commit_group;" ::: "memory");
    };

    auto convF = [&](int c) {
        unsigned fpb = base + OFF_F + (unsigned)(c % 2) * 32768u;
        unsigned th = base + OFF_CV + (unsigned)(c % 2) * 32768u;
        unsigned tl = th + 16384u;
#pragma unroll
        for (int kq = 0; kq < 4; kq++) {
            int kstart = ckg * 8 + kq * 16;
            unsigned hw[4], lw[4];
#pragma unroll
            for (int w2 = 0; w2 < 4; w2++) {
                float x0 = lds_f32(fpb + (unsigned)(((kstart + 2 * w2) * 128 + cd) * 4));
                float x1 = lds_f32(fpb + (unsigned)(((kstart + 2 * w2 + 1) * 128 + cd) * 4));
                split_pair_fast(x0, x1, hw[w2], lw[w2]);
            }
            unsigned off = SWZ((unsigned)(cd * 128 + kstart * 2));
            sts128(th + off, hw[0], hw[1], hw[2], hw[3]);
            sts128(tl + off, lw[0], lw[1], lw[2], lw[3]);
        }
    };

    issueAF(0);
    issueAF(1);
    asm volatile("cp.async.wait_group 1;" ::: "memory");
    __syncthreads();
    convF(0);

    for (int c = 0; c < 64; c++) {
        asm volatile("cp.async.wait_group 0;" ::: "memory");
        __syncthreads();
        if (c + 2 < 64) issueAF(c + 2);
        if (c + 1 < 64) convF(c + 1);

        unsigned astage = base + OFF_A + (unsigned)(c % 3) * 32768u;
        unsigned sAh = astage, sAl = astage + 16384u;
        unsigned cvb = base + OFF_CV + (unsigned)(c % 2) * 32768u;
        unsigned sBh = cvb, sBl = cvb + 16384u;
#pragma unroll
        for (int kk = 0; kk < 4; kk++) {
            unsigned ca = (a_c0 + (unsigned)(kk * 32)) ^ msk;
            unsigned cb = (b_c0 + (unsigned)(kk * 32)) ^ msk;
            unsigned ah[4][4], al[4][4], bh[2][4], bl[2][4];
#pragma unroll
            for (int mt = 0; mt < 4; mt++) {
                ldm4(ah[mt], sAh + a_row[mt] + ca);
                ldm4(al[mt], sAl + a_row[mt] + ca);
            }
#pragma unroll
            for (int np = 0; np < 2; np++) {
                ldm4(bh[np], sBh + b_row[np] + cb);
                ldm4(bl[np], sBl + b_row[np] + cb);
            }
#pragma unroll
            for (int mt = 0; mt < 4; mt++)
#pragma unroll
                for (int nt = 0; nt < 4; nt++)
                    mma_bf16(acc[mt][nt], ah[mt], &bh[nt >> 1][(nt & 1) * 2]);
#pragma unroll
            for (int mt = 0; mt < 4; mt++)
#pragma unroll
                for (int nt = 0; nt < 4; nt++)
                    mma_bf16(acc[mt][nt], ah[mt], &bl[nt >> 1][(nt & 1) * 2]);
#pragma unroll
            for (int mt = 0; mt < 4; mt++)
#pragma unroll
                for (int nt = 0; nt < 4; nt++)
                    mma_bf16(acc[mt][nt], al[mt], &bh[nt >> 1][(nt & 1) * 2]);
        }
    }

#pragma unroll
    for (int mt = 0; mt < 4; mt++) {
#pragma unroll
        for (int nt = 0; nt < 4; nt++) {
            int r0 = wm + mt * 16 + (lane >> 2);
            int c0 = wn + nt * 8 + (lane & 3) * 2;
            unsigned short h0, l0, h1, l1, h2, l2, h3, l3;
            split1(acc[mt][nt][0], h0, l0);
            split1(acc[mt][nt][1], h1, l1);
            split1(acc[mt][nt][2], h2, l2);
            split1(acc[mt][nt][3], h3, l3);
            size_t o01 = cbase + (size_t)r0 * DD + c0;
            size_t o23 = cbase + (size_t)(r0 + 8) * DD + c0;
            *(unsigned*)(g_ABhi + o01) = (unsigned)h0 | ((unsigned)h1 << 16);
            *(unsigned*)(g_ABlo + o01) = (unsigned)l0 | ((unsigned)l1 << 16);
            *(unsigned*)(g_ABhi + o23) = (unsigned)h2 | ((unsigned)h3 << 16);
            *(unsigned*)(g_ABlo + o23) = (unsigned)l2 | ((unsigned)l3 << 16);
        }
    }
}

// ---------------------------------------------------------------------------
// gemm_nt_hmma (unchanged from R16)
// ---------------------------------------------------------------------------
#define NTSTAGE_BYTES 65536
#define NT_SMEM (1024 + 3 * NTSTAGE_BYTES)
__global__ void __launch_bounds__(256, 1) gemm_nt_hmma() {
    extern __shared__ char smraw[];
    unsigned base = (smem_u32(smraw) + 1023) & ~1023u;
    int tid = threadIdx.x, wid = tid >> 5, lane = tid & 31;

    int id = blockIdx.x;
    int b = id / 3, mode = id % 3;
    size_t offA = (size_t)b * KK * DD;
    size_t offB = (size_t)(BB + b) * KK * DD;
    size_t offP = (mode == 0) ? offA : offB;
    size_t offQ = (mode == 1) ? offB : offA;
    const __nv_bfloat16* Ph = g_ABhi + offP;
    const __nv_bfloat16* Pl = g_ABlo + offP;
    const __nv_bfloat16* Qh = g_ABhi + offQ;
    const __nv_bfloat16* Ql = g_ABlo + offQ;
    float* C = (mode < 2) ? g_S + (size_t)(b * 2 + mode) * KK * KK
                          : g_R + (size_t)b * KK * KK;
    float* CT = g_RT + (size_t)b * KK * KK;

    int wm = (wid & 1) * 64, wn = (wid >> 1) * 32;

    float acc[4][4][4];
#pragma unroll
    for (int mt = 0; mt < 4; mt++)
#pragma unroll
        for (int nt = 0; nt < 4; nt++)
#pragma unroll
            for (int i = 0; i < 4; i++) acc[mt][nt][i] = 0.0f;

    unsigned msk = (unsigned)((lane & 7) << 4);
    unsigned a_c0 = (unsigned)((lane >> 4) * 16);
    unsigned b_c0 = (unsigned)(((lane >> 3) & 1) * 16);
    unsigned a_row[4], b_row[2];
#pragma unroll
    for (int mt = 0; mt < 4; mt++)
        a_row[mt] = (unsigned)((wm + mt * 16 + (lane & 15)) * 128);
#pragma unroll
    for (int np = 0; np < 2; np++)
        b_row[np] = (unsigned)((wn + np * 16 + ((lane >> 4) << 3) + (lane & 7)) * 128);

    auto issue = [&](int c) {
        unsigned stage = base + 1024 + (unsigned)(c % 3) * NTSTAGE_BYTES;
        int k0 = c * 64;
#pragma unroll
        for (int u = 0; u < 16; u++) {
            int tile = u >> 2;
            if (mode < 2 && tile >= 2) continue;
            int v = tid + (u & 3) * 256;
            int r = v >> 3, s = v & 7;
            unsigned sa = stage + tile * 16384 + SWZ((unsigned)(r * 128 + s * 16));
            const __nv_bfloat16* g;
            if (tile == 0)      g = Ph;
            else if (tile == 1) g = Pl;
            else if (tile == 2) g = Qh;
            else                g = Ql;
            g += (size_t)r * DD + k0 + s * 8;
            asm volatile("cp.async.cg.shared.global [%0], [%1], 16;"
                         :: "r"(sa), "l"(g) : "memory");
        }
        asm volatile("cp.async.commit_group;" ::: "memory");
    };

    issue(0);
    issue(1);
    for (int c = 0; c < 8; c++) {
        if (c < 7)
            asm volatile("cp.async.wait_group 1;" ::: "memory");
        else
            asm volatile("cp.async.wait_group 0;" ::: "memory");
        __syncthreads();
        if (c + 2 < 8) issue(c + 2);
        unsigned stage = base + 1024 + (unsigned)(c % 3) * NTSTAGE_BYTES;
        unsigned sAh = stage, sAl = stage + 16384;
        unsigned sBh = (mode < 2) ? sAh : stage + 32768;
        unsigned sBl = (mode < 2) ? sAl : stage + 49152;
#pragma unroll
        for (int kk = 0; kk < 4; kk++) {
            unsigned ca = (a_c0 + (unsigned)(kk * 32)) ^ msk;
            unsigned cb = (b_c0 + (unsigned)(kk * 32)) ^ msk;
            unsigned ah[4][4], al[4][4], bh[2][4], bl[2][4];
#pragma unroll
            for (int mt = 0; mt < 4; mt++) {
                ldm4(ah[mt], sAh + a_row[mt] + ca);
                ldm4(al[mt], sAl + a_row[mt] + ca);
            }
#pragma unroll
            for (int np = 0; np < 2; np++) {
                ldm4(bh[np], sBh + b_row[np] + cb);
                ldm4(bl[np], sBl + b_row[np] + cb);
            }
#pragma unroll
            for (int mt = 0; mt < 4; mt++)
#pragma unroll
                for (int nt = 0; nt < 4; nt++)
                    mma_bf16(acc[mt][nt], ah[mt], &bh[nt >> 1][(nt & 1) * 2]);
#pragma unroll
            for (int mt = 0; mt < 4; mt++)
#pragma unroll
                for (int nt = 0; nt < 4; nt++)
                    mma_bf16(acc[mt][nt], ah[mt], &bl[nt >> 1][(nt & 1) * 2]);
#pragma unroll
            for (int mt = 0; mt < 4; mt++)
#pragma unroll
                for (int nt = 0; nt < 4; nt++)
                    mma_bf16(acc[mt][nt], al[mt], &bh[nt >> 1][(nt & 1) * 2]);
        }
    }

#pragma unroll
    for (int mt = 0; mt < 4; mt++) {
#pragma unroll
        for (int nt = 0; nt < 4; nt++) {
            int r0 = wm + mt * 16 + (lane >> 2);
            int c0 = wn + nt * 8 + (lane & 3) * 2;
            float v0 = acc[mt][nt][0], v1 = acc[mt][nt][1];
            float v2 = acc[mt][nt][2], v3 = acc[mt][nt][3];
            if (mode < 2) {
                if (r0 == c0) v0 += REGC;
                if (r0 == c0 + 1) v1 += REGC;
                if (r0 + 8 == c0) v2 += REGC;
                if (r0 + 8 == c0 + 1) v3 += REGC;
            }
            C[r0 * KK + c0] = v0;
            C[r0 * KK + c0 + 1] = v1;
            C[(r0 + 8) * KK + c0] = v2;
            C[(r0 + 8) * KK + c0 + 1] = v3;
            if (mode == 2) {
                CT[c0 * KK + r0] = v0;
                CT[(c0 + 1) * KK + r0] = v1;
                CT[c0 * KK + r0 + 8] = v2;
                CT[(c0 + 1) * KK + r0 + 8] = v3;
            }
        }
    }
}

// ---------------------------------------------------------------------------
// invert_mask (unchanged from R16)
// ---------------------------------------------------------------------------
#define MST 132
#define CST 36
#define TST 36
#define INV_SMEM ((128 * MST + 128 * CST + 32 * TST) * 4)

__global__ void __launch_bounds__(512, 1)
invert_mask(const float* __restrict__ evx, const float* __restrict__ evy,
            const float* __restrict__ ax,  const float* __restrict__ ay) {
    extern __shared__ float sm[];
    float* M  = sm;
    float* Cs = sm + 128 * MST;
    float* T  = Cs + 128 * CST;
    int id = blockIdx.x;
    int b = id >> 1, dir = id & 1;
    const float* S = g_S + (size_t)id * KK * KK;
    float* Si = g_Sinv + (size_t)id * KK * KK;
    int tid = threadIdx.x;
    int lane = tid & 31;
    int tx = tid & 15, ty = tid >> 4;

    {
        __shared__ float t1[128], u1[128], t2[128], u2[128];
        __shared__ float v1[128], w1[128], v2[128], w2[128];
        __shared__ float red[128];
        __shared__ float sc_main, sc_aux;

        const float* e1p = (dir ? evy : evx) + b * KK;
        const float* e2p = (dir ? evx : evy) + b * KK;
        const float* a1p = (dir ? ay : ax) + b * KK;
        const float* a2p = (dir ? ax : ay) + b * KK;

        float e1 = 0.f, e2 = 0.f, q1 = 0.f, q2 = 0.f;
        if (tid < 128) {
            e1 = fmaxf(e1p[tid], 1e-10f);
            e2 = fmaxf(e2p[tid], 1e-10f);
            q1 = fmaxf(a1p[tid], 1e-10f);
            q2 = fmaxf(a2p[tid], 1e-10f);
            red[tid] = fmaxf(e1, e2);
        }
        __syncthreads();
        for (int off = 64; off; off >>= 1) {
            if (tid < off) red[tid] = fmaxf(red[tid], red[tid + off]);
            __syncthreads();
        }
        if (tid == 0) sc_main = fmaxf(red[0], 1e-10f);
        __syncthreads();
        if (tid < 128) red[tid] = fmaxf(q1, q2);
        __syncthreads();
        for (int off = 64; off; off >>= 1) {
            if (tid < off) red[tid] = fmaxf(red[tid], red[tid + off]);
            __syncthreads();
        }
        if (tid == 0) sc_aux = fmaxf(red[0], 1e-10f);
        __syncthreads();

        if (tid < 128) {
            float r, d;
            r = e1 / sc_main; d = r + 1.0f; t1[tid] = sqrtf(r) / d; u1[tid] = 1.0f / d;
            r = e2 / sc_main; d = r + 1.0f; t2[tid] = sqrtf(r) / d; u2[tid] = 1.0f / d;
            r = q1 / sc_aux;  d = r + 1.0f; v1[tid] = sqrtf(r) / d; w1[tid] = 1.0f / d;
            r = q2 / sc_aux;  d = r + 1.0f; v2[tid] = sqrtf(r) / d; w2[tid] = 1.0f / d;
        }
        __syncthreads();

        __nv_bfloat16* Dp = g_Dbf + (size_t)id * (KK * KK);
        for (int v = tid; v < KK * KK; v += 512) {
            int i = v >> 7, j = v & 127;
            float mr = t2[i] - t1[j], mi = u2[i] - u1[j];
            float ar = v2[i] - v1[j], ai = w2[i] - w1[j];
            Dp[v] = __float2bfloat16(100.0f * (mr * mr + mi * mi)
                                   + 25.0f * (ar * ar + ai * ai));
        }
    }

#pragma unroll
    for (int u = 0; u < 8; u++) {
        int v = tid + u * 512;
        int m = v >> 5, c4 = (v & 31) << 2;
        *(float4*)(M + m * MST + c4) = *(const float4*)(S + m * 128 + c4);
    }
    __syncthreads();

    for (int p = 0; p < 4; p++) {
        int p0 = p * 32;
#pragma unroll
        for (int u = 0; u < 2; u++) {
            int v = tid + u * 512;
            int i = v >> 3, q4 = (v & 7) << 2;
            *(float4*)(Cs + i * CST + q4) = *(const float4*)(M + i * MST + p0 + q4);
        }
        __syncthreads();

        if (tid < 32) {
            float reg[32];
#pragma unroll
            for (int i = 0; i < 32; i++)
                reg[i] = M[(p0 + i) * MST + p0 + lane];
#pragma unroll
            for (int j = 0; j < 32; j++) {
                float piv = __shfl_sync(0xffffffffu, reg[j], j);
                float pivinv = 1.0f / piv;
                float rowj = (lane == j) ? pivinv : reg[j] * pivinv;
#pragma unroll
                for (int i = 0; i < 32; i++) {
                    if (i == j) continue;
                    float f = __shfl_sync(0xffffffffu, reg[i], j);
                    reg[i] = (lane == j) ? (-f * pivinv) : fmaf(-f, rowj, reg[i]);
                }
                reg[j] = rowj;
            }
#pragma unroll
            for (int i = 0; i < 32; i++)
                T[i * TST + lane] = reg[i];
        }
        __syncthreads();

        {
            int qr = ty;
            int cb = tx * 8;
            float out[8];
#pragma unroll
            for (int a = 0; a < 8; a++) out[a] = 0.0f;
            for (int r = 0; r < 32; r++) {
                float tq = T[qr * TST + r];
                const float* Mr = M + (p0 + r) * MST + cb;
#pragma unroll
                for (int a = 0; a < 8; a += 4) {
                    float4 mv = *(const float4*)(Mr + a);
                    out[a + 0] += tq * mv.x;
                    out[a + 1] += tq * mv.y;
                    out[a + 2] += tq * mv.z;
                    out[a + 3] += tq * mv.w;
                }
            }
            __syncthreads();
#pragma unroll
            for (int a = 0; a < 8; a++) {
                int l = cb + a;
                float vv = (l >= p0 && l < p0 + 32) ? T[qr * TST + (l - p0)] : out[a];
                M[(p0 + qr) * MST + l] = vv;
            }
            __syncthreads();
        }

        {
            ull acc2[3][4];
#pragma unroll
            for (int r = 0; r < 3; r++)
#pragma unroll
                for (int c = 0; c < 4; c++) acc2[r][c] = 0ULL;
            for (int q = 0; q < 32; q++) {
                const float* Mp = M + (p0 + q) * MST + tx * 8;
                ull b0 = *(const ull*)(Mp + 0);
                ull b1 = *(const ull*)(Mp + 2);
                ull b2 = *(const ull*)(Mp + 4);
                ull b3 = *(const ull*)(Mp + 6);
#pragma unroll
                for (int r = 0; r < 3; r++) {
                    int z = ty + 32 * r;
                    int i = (z < p0) ? z : z + 32;
                    float av = Cs[i * CST + q];
                    ull a2 = pack2(av, av);
                    ffma2(acc2[r][0], a2, b0);
                    ffma2(acc2[r][1], a2, b1);
                    ffma2(acc2[r][2], a2, b2);
                    ffma2(acc2[r][3], a2, b3);
                }
            }
#pragma unroll
            for (int r = 0; r < 3; r++) {
                int z = ty + 32 * r;
                int i = (z < p0) ? z : z + 32;
#pragma unroll
                for (int c = 0; c < 4; c++) {
                    int l = tx * 8 + 2 * c;
                    float lo, hi;
                    unpack2(acc2[r][c], lo, hi);
                    float* Mp = M + i * MST + l;
                    bool inP0 = (l >= p0 && l < p0 + 32);
                    bool inP1 = (l + 1 >= p0 && l + 1 < p0 + 32);
                    float o0 = (inP0 ? 0.0f : Mp[0]) - lo;
                    float o1 = (inP1 ? 0.0f : Mp[1]) - hi;
                    Mp[0] = o0;
                    Mp[1] = o1;
                }
            }
            __syncthreads();
        }
    }

#pragma unroll
    for (int u = 0; u < 8; u++) {
        int v = tid + u * 512;
        int m = v >> 5, c4 = (v & 31) << 2;
        *(float4*)(Si + m * 128 + c4) = *(const float4*)(M + m * MST + c4);
    }
}

// ---------------------------------------------------------------------------
// solve_hmma: ONE Neumann correction (residual ~rho^2 <= 1.6e-4 worst case).
// pass 0: X0 = R*Sinv; out = X0 - (D o X0)*Sinv.
// ---------------------------------------------------------------------------
#define SOLVE_SMEM (1024 + 3 * 65536 + 32768)

__device__ __forceinline__ unsigned XSWZ(int row, unsigned cb) {
    return (unsigned)row * 512u + (cb ^ (unsigned)((row & 31) << 4));
}
__device__ __forceinline__ unsigned DSWZ(int row, unsigned cb) {
    return (unsigned)row * 256u + (cb ^ (unsigned)((row & 15) << 4));
}

__device__ __forceinline__ void conv_store8(const float* f, unsigned th, unsigned tl,
                                            unsigned off) {
    unsigned hw[4], lw[4];
#pragma unroll
    for (int w2 = 0; w2 < 4; w2++) {
        unsigned short h0, l0, h1, l1;
        split1(f[2 * w2], h0, l0); split1(f[2 * w2 + 1], h1, l1);
        hw[w2] = (unsigned)h0 | ((unsigned)h1 << 16);
        lw[w2] = (unsigned)l0 | ((unsigned)l1 << 16);
    }
    sts128(th + off, hw[0], hw[1], hw[2], hw[3]);
    sts128(tl + off, lw[0], lw[1], lw[2], lw[3]);
}

__device__ __forceinline__ void solve_K128(unsigned sT, unsigned sS,
                                           const unsigned* a_row, const unsigned* b_row,
                                           unsigned a_c0, unsigned b_c0, unsigned msk,
                                           float acc[4][4][4]) {
#pragma unroll
    for (int mt = 0; mt < 4; mt++)
#pragma unroll
        for (int nt = 0; nt < 4; nt++)
#pragma unroll
            for (int i = 0; i < 4; i++) acc[mt][nt][i] = 0.0f;
#pragma unroll
    for (int kc = 0; kc < 2; kc++) {
        unsigned tTh = sT + (unsigned)kc * 32768u, tTl = tTh + 16384u;
        unsigned tSh = sS + (unsigned)kc * 32768u, tSl = tSh + 16384u;
#pragma unroll
        for (int kk = 0; kk < 4; kk++) {
            unsigned ca = (a_c0 + (unsigned)(kk * 32)) ^ msk;
            unsigned cb = (b_c0 + (unsigned)(kk * 32)) ^ msk;
            unsigned ah[4][4], al[4][4], bh[2][4], bl[2][4];
#pragma unroll
            for (int mt = 0; mt < 4; mt++) {
                ldm4(ah[mt], tTh + a_row[mt] + ca);
                ldm4(al[mt], tTl + a_row[mt] + ca);
            }
#pragma unroll
            for (int np = 0; np < 2; np++) {
                ldm4(bh[np], tSh + b_row[np] + cb);
                ldm4(bl[np], tSl + b_row[np] + cb);
            }
#pragma unroll
            for (int mt = 0; mt < 4; mt++)
#pragma unroll
                for (int nt = 0; nt < 4; nt++)
                    mma_bf16(acc[mt][nt], ah[mt], &bh[nt >> 1][(nt & 1) * 2]);
#pragma unroll
            for (int mt = 0; mt < 4; mt++)
#pragma unroll
                for (int nt = 0; nt < 4; nt++)
                    mma_bf16(acc[mt][nt], ah[mt], &bl[nt >> 1][(nt & 1) * 2]);
#pragma unroll
            for (int mt = 0; mt < 4; mt++)
#pragma unroll
                for (int nt = 0; nt < 4; nt++)
                    mma_bf16(acc[mt][nt], al[mt], &bh[nt >> 1][(nt & 1) * 2]);
        }
    }
}

__global__ void __launch_bounds__(256, 1) solve_hmma(float* __restrict__ out) {
    extern __shared__ char smraw[];
    unsigned base = (smem_u32(smraw) + 1023) & ~1023u;
    unsigned sX  = base;
    unsigned sS  = base + 65536;
    unsigned sT  = base + 131072;
    unsigned sDb = base + 196608;
    int id = blockIdx.x;
    int b = id >> 1, dir = id & 1;
    const float* Sinv = g_Sinv + (size_t)id * KK * KK;
    const char* Dm = (const char*)(g_Dbf + (size_t)id * KK * KK);
    const float* Rb = (dir ? g_RT : g_R) + (size_t)b * KK * KK;
    float* Cout = out + (size_t)(dir ? BB * KK * KK : 0) + (size_t)b * KK * KK;
    int tid = threadIdx.x, wid = tid >> 5, lane = tid & 31;

    int wm = (wid & 1) * 64, wn = (wid >> 1) * 32;
    unsigned msk = (unsigned)((lane & 7) << 4);
    unsigned a_c0 = (unsigned)((lane >> 4) * 16);
    unsigned b_c0 = (unsigned)(((lane >> 3) & 1) * 16);
    unsigned a_row[4], b_row[2];
#pragma unroll
    for (int mt = 0; mt < 4; mt++)
        a_row[mt] = (unsigned)((wm + mt * 16 + (lane & 15)) * 128);
#pragma unroll
    for (int np = 0; np < 2; np++)
        b_row[np] = (unsigned)((wn + np * 16 + ((lane >> 4) << 3) + (lane & 7)) * 128);

    int crow = tid & 127, ckc = tid >> 7;
    unsigned convTh = sT + (unsigned)ckc * 32768u, convTl = convTh + 16384u;
    unsigned convSh = sS + (unsigned)ckc * 32768u, convSl = convSh + 16384u;

#pragma unroll
    for (int u = 0; u < 16; u++) {
        int v = tid + u * 256;
        int row = v >> 5, seg = v & 31;
        asm volatile("cp.async.cg.shared.global [%0], [%1], 16;"
                     :: "r"(sX + XSWZ(row, (unsigned)(seg * 16))),
                        "l"((const float4*)Sinv + v) : "memory");
    }
    asm volatile("cp.async.commit_group;" ::: "memory");
#pragma unroll
    for (int u = 0; u < 8; u++) {
        int v = tid + u * 256;
        int row = v >> 4, seg = v & 15;
        asm volatile("cp.async.cg.shared.global [%0], [%1], 16;"
                     :: "r"(sDb + DSWZ(row, (unsigned)(seg * 16))),
                        "l"(Dm + (size_t)v * 16) : "memory");
    }
    asm volatile("cp.async.commit_group;" ::: "memory");
    asm volatile("cp.async.wait_group 1;" ::: "memory");
    __syncthreads();

    // conv Sinv -> S tiles (symmetry)
#pragma unroll
    for (int s = 0; s < 8; s++) {
        unsigned cb = (unsigned)(ckc * 256 + s * 32);
        float4 fa = lds_f128(sX + XSWZ(crow, cb));
        float4 fb = lds_f128(sX + XSWZ(crow, cb + 16));
        float f[8] = {fa.x, fa.y, fa.z, fa.w, fb.x, fb.y, fb.z, fb.w};
        conv_store8(f, convSh, convSl, SWZ((unsigned)(crow * 128 + s * 16)));
    }
    __syncthreads();

    // load R -> X
#pragma unroll
    for (int u = 0; u < 16; u++) {
        int v = tid + u * 256;
        int row = v >> 5, seg = v & 31;
        asm volatile("cp.async.cg.shared.global [%0], [%1], 16;"
                     :: "r"(sX + XSWZ(row, (unsigned)(seg * 16))),
                        "l"((const float4*)Rb + v) : "memory");
    }
    asm volatile("cp.async.commit_group;" ::: "memory");
    asm volatile("cp.async.wait_group 0;" ::: "memory");
    __syncthreads();

    // conv R -> T tiles
#pragma unroll
    for (int s = 0; s < 8; s++) {
        unsigned cb = (unsigned)(ckc * 256 + s * 32);
        float4 fa = lds_f128(sX + XSWZ(crow, cb));
        float4 fb = lds_f128(sX + XSWZ(crow, cb + 16));
        float f[8] = {fa.x, fa.y, fa.z, fa.w, fb.x, fb.y, fb.z, fb.w};
        conv_store8(f, convTh, convTl, SWZ((unsigned)(crow * 128 + s * 16)));
    }
    __syncthreads();

    float acc0[4][4][4], acc[4][4][4];

    // pass 0: X0 = R * Sinv (acc0 in registers; X0 also to smem for the conv)
    solve_K128(sT, sS, a_row, b_row, a_c0, b_c0, msk, acc0);
    __syncthreads();
#pragma unroll
    for (int mt = 0; mt < 4; mt++) {
#pragma unroll
        for (int nt = 0; nt < 4; nt++) {
            int r0 = wm + mt * 16 + (lane >> 2);
            int c0 = wn + nt * 8 + (lane & 3) * 2;
            sts_v2f(sX + XSWZ(r0, (unsigned)(c0 * 4)), acc0[mt][nt][0], acc0[mt][nt][1]);
            sts_v2f(sX + XSWZ(r0 + 8, (unsigned)(c0 * 4)), acc0[mt][nt][2], acc0[mt][nt][3]);
        }
    }
    __syncthreads();

    // single correction: conv T = D o X0, GEMM, out = X0 - acc
#pragma unroll
    for (int s = 0; s < 8; s++) {
        unsigned cb = (unsigned)(ckc * 256 + s * 32);
        float4 fa = lds_f128(sX + XSWZ(crow, cb));
        float4 fb = lds_f128(sX + XSWZ(crow, cb + 16));
        uint4 dw = lds_u128(sDb + DSWZ(crow, (unsigned)(ckc * 128 + s * 16)));
        float f[8];
        f[0] = fa.x * bf2f((unsigned short)(dw.x & 0xffff));
        f[1] = fa.y * bf2f((unsigned short)(dw.x >> 16));
        f[2] = fa.z * bf2f((unsigned short)(dw.y & 0xffff));
        f[3] = fa.w * bf2f((unsigned short)(dw.y >> 16));
        f[4] = fb.x * bf2f((unsigned short)(dw.z & 0xffff));
        f[5] = fb.y * bf2f((unsigned short)(dw.z >> 16));
        f[6] = fb.z * bf2f((unsigned short)(dw.w & 0xffff));
        f[7] = fb.w * bf2f((unsigned short)(dw.w >> 16));
        conv_store8(f, convTh, convTl, SWZ((unsigned)(crow * 128 + s * 16)));
    }
    __syncthreads();
    solve_K128(sT, sS, a_row, b_row, a_c0, b_c0, msk, acc);
#pragma unroll
    for (int mt = 0; mt < 4; mt++) {
#pragma unroll
        for (int nt = 0; nt < 4; nt++) {
            int r0 = wm + mt * 16 + (lane >> 2);
            int c0 = wn + nt * 8 + (lane & 3) * 2;
            *(float2*)&Cout[r0 * 128 + c0] =
                make_float2(acc0[mt][nt][0] - acc[mt][nt][0],
                            acc0[mt][nt][1] - acc[mt][nt][1]);
            *(float2*)&Cout[(r0 + 8) * 128 + c0] =
                make_float2(acc0[mt][nt][2] - acc[mt][nt][2],
                            acc0[mt][nt][3] - acc[mt][nt][3]);
        }
    }
}

// ---------------------------------------------------------------------------
extern "C" void kernel_launch(void* const* d_in, const int* in_sizes, int n_in,
                              void* d_out, int out_size) {
    const float* feat_x  = (const float*)d_in[0];
    const float* feat_y  = (const float*)d_in[1];
    const float* evals_x = (const float*)d_in[2];
    const float* evals_y = (const float*)d_in[3];
    const float* evecs_x = (const float*)d_in[4];
    const float* evecs_y = (const float*)d_in[5];
    const float* aux_x   = (const float*)d_in[6];
    const float* aux_y   = (const float*)d_in[7];
    float* out = (float*)d_out;

    split_E<<<dim3(8192, 2), 256>>>(evecs_x, evecs_y);

    cudaFuncSetAttribute(mma_proj, cudaFuncAttributeMaxDynamicSharedMemorySize, MMA_SMEM);
    mma_proj<<<dim3(4, 32), 256, MMA_SMEM>>>(feat_x, feat_y);

    cudaFuncSetAttribute(gemm_nt_hmma, cudaFuncAttributeMaxDynamicSharedMemorySize, NT_SMEM);
    gemm_nt_hmma<<<48, 256, NT_SMEM>>>();

    cudaFuncSetAttribute(invert_mask, cudaFuncAttributeMaxDynamicSharedMemorySize, INV_SMEM);
    invert_mask<<<32, 512, INV_SMEM>>>(evals_x, evals_y, aux_x, aux_y);

    cudaFuncSetAttribute(solve_hmma, cudaFuncAttributeMaxDynamicSharedMemorySize, SOLVE_SMEM);
    solve_hmma<<<32, 256, SOLVE_SMEM>>>(out);
}